// round 1
// baseline (speedup 1.0000x reference)
#include <cuda_runtime.h>
#include <math.h>

#define NN 50000
#define NE 800000
#define CD 128
#define AH 64

// ---------------- scratch (static device globals; no runtime allocation) ----------
__device__ float g_nsq[NN];
__device__ float g_ns[NN];
__device__ float g_n3sq[NN];
__device__ float g_n4sq[NN];
__device__ float g_s4[NN];
__device__ int   g_deg[NN];
__device__ int   g_rowptr[NN + 1];
__device__ int   g_cursor[NN];
__device__ int   g_csr[NE];
__device__ float g_aggc[(size_t)NN * CD];
__device__ float g_agge[(size_t)NN * CD];
__device__ float g_x1[(size_t)NN * CD];
__device__ float g_x2[(size_t)NN * CD];
__device__ float g_h[(size_t)4 * NN * AH];

__device__ __forceinline__ float wredsum(float v) {
#pragma unroll
    for (int o = 16; o; o >>= 1) v += __shfl_xor_sync(0xffffffffu, v, o);
    return v;
}

// ---------------- per-node stats of x: ||x||^2 and sum(x) -------------------------
__global__ void k_stats1(const float* __restrict__ x) {
    int node = blockIdx.x * 8 + (threadIdx.x >> 5);
    if (node >= NN) return;
    int lane = threadIdx.x & 31;
    float4 v = *(const float4*)(x + (size_t)node * CD + lane * 4);
    float sq = v.x * v.x + v.y * v.y + v.z * v.z + v.w * v.w;
    float s  = v.x + v.y + v.z + v.w;
    sq = wredsum(sq);
    s  = wredsum(s);
    if (lane == 0) { g_nsq[node] = sq; g_ns[node] = s; }
}

// ---------------- degree histogram ------------------------------------------------
__global__ void k_deg(const int* __restrict__ row) {
    int e = blockIdx.x * blockDim.x + threadIdx.x;
    if (e < NE) atomicAdd(&g_deg[row[e]], 1);
}

// ---------------- single-block exclusive scan -> rowptr ---------------------------
__global__ void k_scan() {
    __shared__ int sh[1024];
    __shared__ int carry;
    if (threadIdx.x == 0) carry = 0;
    __syncthreads();
    for (int base = 0; base < NN; base += 1024) {
        int i = base + threadIdx.x;
        int v = (i < NN) ? g_deg[i] : 0;
        sh[threadIdx.x] = v;
        __syncthreads();
        for (int off = 1; off < 1024; off <<= 1) {
            int t = (threadIdx.x >= off) ? sh[threadIdx.x - off] : 0;
            __syncthreads();
            sh[threadIdx.x] += t;
            __syncthreads();
        }
        if (i < NN) g_rowptr[i + 1] = carry + sh[threadIdx.x];
        __syncthreads();
        if (threadIdx.x == 0) carry += sh[1023];
        __syncthreads();
    }
    if (threadIdx.x == 0) g_rowptr[0] = 0;
}

// ---------------- CSR scatter -----------------------------------------------------
__global__ void k_scatter(const int* __restrict__ row, const int* __restrict__ col) {
    int e = blockIdx.x * blockDim.x + threadIdx.x;
    if (e >= NE) return;
    int r = row[e];
    int p = atomicAdd(&g_cursor[r], 1);
    g_csr[g_rowptr[r] + p] = col[e];
}

// ---------------- fused layer-1 edge weights + aggregation (warp per node) --------
__global__ void k_agg1(const float* __restrict__ x) {
    int node = blockIdx.x * 8 + (threadIdx.x >> 5);
    if (node >= NN) return;
    int lane = threadIdx.x & 31;
    const float4* xb = (const float4*)x;
    float4 xi = xb[(size_t)node * 32 + lane];
    float nsq_i = g_nsq[node], ns_i = g_ns[node];
    int s = g_rowptr[node], t = g_rowptr[node + 1];
    float4 ac = make_float4(0.f, 0.f, 0.f, 0.f);
    float4 ae = make_float4(0.f, 0.f, 0.f, 0.f);
    for (int j = s; j < t; j++) {
        int c = g_csr[j];
        float4 v = xb[(size_t)c * 32 + lane];
        float d = xi.x * v.x + xi.y * v.y + xi.z * v.z + xi.w * v.w;
        d = wredsum(d);
        float nsq_c = g_nsq[c], ns_c = g_ns[c];
        float wc = d / fmaxf(sqrtf(nsq_i * nsq_c), 1e-8f);
        float q = nsq_i + nsq_c - 2.f * d + 2e-6f * (ns_i - ns_c) + 1.28e-10f;
        float we = sqrtf(fmaxf(q, 0.f));
        ac.x += wc * v.x; ac.y += wc * v.y; ac.z += wc * v.z; ac.w += wc * v.w;
        ae.x += we * v.x; ae.y += we * v.y; ae.z += we * v.z; ae.w += we * v.w;
    }
    float inv = 1.f / (float)max(t - s, 1);
    float4 oc = make_float4(ac.x * inv, ac.y * inv, ac.z * inv, ac.w * inv);
    float4 oe = make_float4(ae.x * inv, ae.y * inv, ae.z * inv, ae.w * inv);
    ((float4*)g_aggc)[(size_t)node * 32 + lane] = oc;
    ((float4*)g_agge)[(size_t)node * 32 + lane] = oe;
}

// ---------------- per-node stats of x3, x4 ----------------------------------------
__global__ void k_stats2(const float* __restrict__ x3, const float* __restrict__ x4) {
    int node = blockIdx.x * 8 + (threadIdx.x >> 5);
    if (node >= NN) return;
    int lane = threadIdx.x & 31;
    float4 a = ((const float4*)x3)[(size_t)node * 32 + lane];
    float4 b = ((const float4*)x4)[(size_t)node * 32 + lane];
    float s3  = a.x * a.x + a.y * a.y + a.z * a.z + a.w * a.w;
    float s4q = b.x * b.x + b.y * b.y + b.z * b.z + b.w * b.w;
    float s4s = b.x + b.y + b.z + b.w;
    s3 = wredsum(s3); s4q = wredsum(s4q); s4s = wredsum(s4s);
    if (lane == 0) { g_n3sq[node] = s3; g_n4sq[node] = s4q; g_s4[node] = s4s; }
}

// ---------------- fused layer-2 edge weights + aggregation ------------------------
__global__ void k_agg2(const float* __restrict__ x3, const float* __restrict__ x4) {
    int node = blockIdx.x * 8 + (threadIdx.x >> 5);
    if (node >= NN) return;
    int lane = threadIdx.x & 31;
    const float4* x3b = (const float4*)x3;
    const float4* x4b = (const float4*)x4;
    float4 a3 = x3b[(size_t)node * 32 + lane];
    float4 a4 = x4b[(size_t)node * 32 + lane];
    float n3i = g_n3sq[node], n4i = g_n4sq[node], s4i = g_s4[node];
    int s = g_rowptr[node], t = g_rowptr[node + 1];
    float4 ac = make_float4(0.f, 0.f, 0.f, 0.f);
    float4 ae = make_float4(0.f, 0.f, 0.f, 0.f);
    for (int j = s; j < t; j++) {
        int c = g_csr[j];
        float4 v3 = x3b[(size_t)c * 32 + lane];
        float4 v4 = x4b[(size_t)c * 32 + lane];
        float d3 = a3.x * v3.x + a3.y * v3.y + a3.z * v3.z + a3.w * v3.w;
        float d4 = a4.x * v4.x + a4.y * v4.y + a4.z * v4.z + a4.w * v4.w;
        d3 = wredsum(d3);
        d4 = wredsum(d4);
        float wc = d3 / fmaxf(sqrtf(n3i * g_n3sq[c]), 1e-8f);
        float q = n4i + g_n4sq[c] - 2.f * d4 + 2e-6f * (s4i - g_s4[c]) + 1.28e-10f;
        float we = sqrtf(fmaxf(q, 0.f));
        ac.x += wc * v3.x; ac.y += wc * v3.y; ac.z += wc * v3.z; ac.w += wc * v3.w;
        ae.x += we * v4.x; ae.y += we * v4.y; ae.z += we * v4.z; ae.w += we * v4.w;
    }
    float inv = 1.f / (float)max(t - s, 1);
    float4 oc = make_float4(ac.x * inv, ac.y * inv, ac.z * inv, ac.w * inv);
    float4 oe = make_float4(ae.x * inv, ae.y * inv, ae.z * inv, ae.w * inv);
    ((float4*)g_aggc)[(size_t)node * 32 + lane] = oc;
    ((float4*)g_agge)[(size_t)node * 32 + lane] = oe;
}

// ---------------- generic fp32 GEMM: C = act(A1@B1 [+ A2@B2] + bias) --------------
// A: [M,128] row-major. B: [128,BN] row-major. C: [M,BN]. ACT: 0=none,1=relu,2=tanh
template <int BN, int TN, int ACT>
__global__ __launch_bounds__(256) void k_gemm(
    const float* __restrict__ A1, const float* __restrict__ A2,
    const float* __restrict__ B1, const float* __restrict__ B2,
    const float* __restrict__ bias, float* __restrict__ Cout, int M) {
    const int BM = 128, BK = 16, TM = 8;
    const int NCG = BN / TN;
    __shared__ float As[BK][BM + 4];
    __shared__ float Bs[BK][BN];
    int tid = threadIdx.x;
    int m0 = blockIdx.x * BM;
    int tn = (tid % NCG) * TN;
    int tm = (tid / NCG) * TM;
    float acc[TM][TN];
#pragma unroll
    for (int i = 0; i < TM; i++)
#pragma unroll
        for (int j = 0; j < TN; j++) acc[i][j] = 0.f;

    for (int half = 0; half < 2; half++) {
        const float* A = half ? A2 : A1;
        const float* B = half ? B2 : B1;
        if (A == nullptr) break;
        for (int k0 = 0; k0 < CD; k0 += BK) {
            // A tile: 128x16 floats, transposed into As[k][m]
#pragma unroll
            for (int p = 0; p < 2; p++) {
                int f = tid + p * 256;      // float4 id 0..511
                int r = f >> 2;             // row within tile
                int kc = (f & 3) * 4;       // k offset
                float4 av = (m0 + r < M)
                    ? *(const float4*)(A + (size_t)(m0 + r) * CD + k0 + kc)
                    : make_float4(0.f, 0.f, 0.f, 0.f);
                As[kc + 0][r] = av.x;
                As[kc + 1][r] = av.y;
                As[kc + 2][r] = av.z;
                As[kc + 3][r] = av.w;
            }
            // B tile: 16xBN
#pragma unroll
            for (int p = 0; p < BN / 64; p++) {
                int f = tid + p * 256;
                int kr = f / (BN / 4);
                int nc = (f % (BN / 4)) * 4;
                float4 bv = *(const float4*)(B + (size_t)(k0 + kr) * BN + nc);
                *(float4*)&Bs[kr][nc] = bv;
            }
            __syncthreads();
#pragma unroll
            for (int kk = 0; kk < BK; kk++) {
                float ra[TM], rb[TN];
#pragma unroll
                for (int i = 0; i < TM; i++) ra[i] = As[kk][tm + i];
#pragma unroll
                for (int j = 0; j < TN; j++) rb[j] = Bs[kk][tn + j];
#pragma unroll
                for (int i = 0; i < TM; i++)
#pragma unroll
                    for (int j = 0; j < TN; j++) acc[i][j] += ra[i] * rb[j];
            }
            __syncthreads();
        }
    }
#pragma unroll
    for (int i = 0; i < TM; i++) {
        int m = m0 + tm + i;
        if (m >= M) break;
#pragma unroll
        for (int j = 0; j < TN; j++) {
            float v = acc[i][j] + bias[tn + j];
            if (ACT == 1) v = fmaxf(v, 0.f);
            if (ACT == 2) asm("tanh.approx.f32 %0, %0;" : "+f"(v));
            Cout[(size_t)m * BN + tn + j] = v;
        }
    }
}

// ---------------- attention pooling (warp per node) -------------------------------
__global__ void k_pool(const float* __restrict__ x3, const float* __restrict__ x4,
                       const float* __restrict__ attW2, float* __restrict__ emb) {
    int node = blockIdx.x * 8 + (threadIdx.x >> 5);
    if (node >= NN) return;
    int lane = threadIdx.x & 31;
    float w2a = attW2[lane], w2b = attW2[lane + 32];
    float wk[4];
#pragma unroll
    for (int k = 0; k < 4; k++) {
        const float* H = g_h + (size_t)k * NN * AH + (size_t)node * AH;
        float p = H[lane] * w2a + H[lane + 32] * w2b;
        wk[k] = wredsum(p);
    }
    float m = fmaxf(fmaxf(wk[0], wk[1]), fmaxf(wk[2], wk[3]));
    float e0 = __expf(wk[0] - m), e1 = __expf(wk[1] - m);
    float e2 = __expf(wk[2] - m), e3 = __expf(wk[3] - m);
    float inv = 1.f / (e0 + e1 + e2 + e3);
    float b0 = e0 * inv, b1 = e1 * inv, b2 = e2 * inv, b3 = e3 * inv;
    float4 v1 = ((const float4*)g_x1)[(size_t)node * 32 + lane];
    float4 v2 = ((const float4*)g_x2)[(size_t)node * 32 + lane];
    float4 v3 = ((const float4*)x3)[(size_t)node * 32 + lane];
    float4 v4 = ((const float4*)x4)[(size_t)node * 32 + lane];
    float4 r;
    r.x = b0 * v1.x + b1 * v2.x + b2 * v3.x + b3 * v4.x;
    r.y = b0 * v1.y + b1 * v2.y + b2 * v3.y + b3 * v4.y;
    r.z = b0 * v1.z + b1 * v2.z + b2 * v3.z + b3 * v4.z;
    r.w = b0 * v1.w + b1 * v2.w + b2 * v3.w + b3 * v4.w;
    ((float4*)emb)[(size_t)node * 32 + lane] = r;
}

// ---------------- host ------------------------------------------------------------
extern "C" void kernel_launch(void* const* d_in, const int* in_sizes, int n_in,
                              void* d_out, int out_size) {
    const float* x     = (const float*)d_in[0];
    const int*   row   = (const int*)d_in[1];
    const int*   col   = (const int*)d_in[2];
    const float* Wl0   = (const float*)d_in[3];
    const float* bl0   = (const float*)d_in[4];
    const float* Wr0   = (const float*)d_in[5];
    const float* Wl1   = (const float*)d_in[6];
    const float* bl1   = (const float*)d_in[7];
    const float* Wr1   = (const float*)d_in[8];
    const float* attW1 = (const float*)d_in[9];
    const float* attb1 = (const float*)d_in[10];
    const float* attW2 = (const float*)d_in[11];

    float* out = (float*)d_out;
    float* emb = out;
    float* x3  = out + (size_t)NN * CD;
    float* x4  = out + (size_t)2 * NN * CD;

    void *pdeg, *pcur;
    float *aggc, *agge, *x1b, *x2b, *hbuf;
    cudaGetSymbolAddress(&pdeg, g_deg);
    cudaGetSymbolAddress(&pcur, g_cursor);
    cudaGetSymbolAddress((void**)&aggc, g_aggc);
    cudaGetSymbolAddress((void**)&agge, g_agge);
    cudaGetSymbolAddress((void**)&x1b, g_x1);
    cudaGetSymbolAddress((void**)&x2b, g_x2);
    cudaGetSymbolAddress((void**)&hbuf, g_h);

    cudaMemsetAsync(pdeg, 0, NN * sizeof(int));
    cudaMemsetAsync(pcur, 0, NN * sizeof(int));

    const int nodeBlocks = (NN + 7) / 8;
    const int edgeBlocks = (NE + 255) / 256;
    const int gB = (NN + 127) / 128;

    k_stats1<<<nodeBlocks, 256>>>(x);
    k_deg<<<edgeBlocks, 256>>>(row);
    k_scan<<<1, 1024>>>();
    k_scatter<<<edgeBlocks, 256>>>(row, col);
    k_agg1<<<nodeBlocks, 256>>>(x);

    // x3 = relu([aggc | x] @ [Wl0 ; Wr0] + bl0),  x4 likewise with agge
    k_gemm<128, 8, 1><<<gB, 256>>>(aggc, x, Wl0, Wr0, bl0, x3, NN);
    k_gemm<128, 8, 1><<<gB, 256>>>(agge, x, Wl0, Wr0, bl0, x4, NN);

    k_stats2<<<nodeBlocks, 256>>>(x3, x4);
    k_agg2<<<nodeBlocks, 256>>>(x3, x4);

    // x1 = [aggc2 | x3] @ [Wl1 ; Wr1] + bl1,  x2 = [agge2 | x4] @ [Wl1 ; Wr1] + bl1
    k_gemm<128, 8, 0><<<gB, 256>>>(aggc, x3, Wl1, Wr1, bl1, x1b, NN);
    k_gemm<128, 8, 0><<<gB, 256>>>(agge, x4, Wl1, Wr1, bl1, x2b, NN);

    // H_k = tanh(X_k @ attW1 + attb1), k in {x1,x2,x3,x4}
    k_gemm<64, 4, 2><<<gB, 256>>>(x1b, nullptr, attW1, nullptr, attb1, hbuf + (size_t)0 * NN * AH, NN);
    k_gemm<64, 4, 2><<<gB, 256>>>(x2b, nullptr, attW1, nullptr, attb1, hbuf + (size_t)1 * NN * AH, NN);
    k_gemm<64, 4, 2><<<gB, 256>>>(x3,  nullptr, attW1, nullptr, attb1, hbuf + (size_t)2 * NN * AH, NN);
    k_gemm<64, 4, 2><<<gB, 256>>>(x4,  nullptr, attW1, nullptr, attb1, hbuf + (size_t)3 * NN * AH, NN);

    k_pool<<<nodeBlocks, 256>>>(x3, x4, attW2, emb);
}

// round 5
// speedup vs baseline: 1.2493x; 1.2493x over previous
#include <cuda_runtime.h>
#include <cuda_bf16.h>
#include <math.h>
#include <stdint.h>

#define NN 50000
#define NE 800000
#define CD 128
#define AH 64

// ---------------- scratch (static device globals) ---------------------------------
__device__ float g_nsq[NN];
__device__ float g_ns[NN];
__device__ float g_n3sq[NN];
__device__ float g_n4sq[NN];
__device__ float g_s4[NN];
__device__ int   g_deg[NN];
__device__ int   g_rowptr[NN + 1];
__device__ int   g_cursor[NN];
__device__ int   g_csr[NE];
__device__ float g_aggc[(size_t)NN * CD];
__device__ float g_agge[(size_t)NN * CD];
__device__ float g_x1[(size_t)NN * CD];
__device__ float g_x2[(size_t)NN * CD];
__device__ float g_h[(size_t)4 * NN * AH];
// split-bf16 transposed weights: [N rows x K cols]
__device__ __nv_bfloat16 g_w0h[128 * 256];
__device__ __nv_bfloat16 g_w0l[128 * 256];
__device__ __nv_bfloat16 g_w1h[128 * 256];
__device__ __nv_bfloat16 g_w1l[128 * 256];
__device__ __nv_bfloat16 g_wah[64 * 128];
__device__ __nv_bfloat16 g_wal[64 * 128];

__device__ __forceinline__ uint32_t smem_u32(const void* p) {
    uint32_t a;
    asm("{ .reg .u64 t; cvta.to.shared.u64 t, %1; cvt.u32.u64 %0, t; }" : "=r"(a) : "l"(p));
    return a;
}

__device__ __forceinline__ float wredsum(float v) {
#pragma unroll
    for (int o = 16; o; o >>= 1) v += __shfl_xor_sync(0xffffffffu, v, o);
    return v;
}

// ---------------- per-node stats of x ---------------------------------------------
__global__ void k_stats1(const float* __restrict__ x) {
    int node = blockIdx.x * 8 + (threadIdx.x >> 5);
    if (node >= NN) return;
    int lane = threadIdx.x & 31;
    float4 v = *(const float4*)(x + (size_t)node * CD + lane * 4);
    float sq = v.x * v.x + v.y * v.y + v.z * v.z + v.w * v.w;
    float s  = v.x + v.y + v.z + v.w;
    sq = wredsum(sq);
    s  = wredsum(s);
    if (lane == 0) { g_nsq[node] = sq; g_ns[node] = s; }
}

// ---------------- CSR build -------------------------------------------------------
__global__ void k_deg(const int* __restrict__ row) {
    int e = blockIdx.x * blockDim.x + threadIdx.x;
    if (e < NE) atomicAdd(&g_deg[row[e]], 1);
}
__global__ void k_scan() {
    __shared__ int sh[1024];
    __shared__ int carry;
    if (threadIdx.x == 0) carry = 0;
    __syncthreads();
    for (int base = 0; base < NN; base += 1024) {
        int i = base + threadIdx.x;
        int v = (i < NN) ? g_deg[i] : 0;
        sh[threadIdx.x] = v;
        __syncthreads();
        for (int off = 1; off < 1024; off <<= 1) {
            int t = (threadIdx.x >= off) ? sh[threadIdx.x - off] : 0;
            __syncthreads();
            sh[threadIdx.x] += t;
            __syncthreads();
        }
        if (i < NN) g_rowptr[i + 1] = carry + sh[threadIdx.x];
        __syncthreads();
        if (threadIdx.x == 0) carry += sh[1023];
        __syncthreads();
    }
    if (threadIdx.x == 0) g_rowptr[0] = 0;
}
__global__ void k_scatter(const int* __restrict__ row, const int* __restrict__ col) {
    int e = blockIdx.x * blockDim.x + threadIdx.x;
    if (e >= NE) return;
    int r = row[e];
    int p = atomicAdd(&g_cursor[r], 1);
    g_csr[g_rowptr[r] + p] = col[e];
}

// ---------------- fused layer-1 edge weights + aggregation ------------------------
__global__ void k_agg1(const float* __restrict__ x) {
    int node = blockIdx.x * 8 + (threadIdx.x >> 5);
    if (node >= NN) return;
    int lane = threadIdx.x & 31;
    const float4* xb = (const float4*)x;
    float4 xi = xb[(size_t)node * 32 + lane];
    float nsq_i = g_nsq[node], ns_i = g_ns[node];
    int s = g_rowptr[node], t = g_rowptr[node + 1];
    float4 ac = make_float4(0.f, 0.f, 0.f, 0.f);
    float4 ae = make_float4(0.f, 0.f, 0.f, 0.f);
    for (int j = s; j < t; j++) {
        int c = g_csr[j];
        float4 v = xb[(size_t)c * 32 + lane];
        float d = xi.x * v.x + xi.y * v.y + xi.z * v.z + xi.w * v.w;
        d = wredsum(d);
        float nsq_c = g_nsq[c], ns_c = g_ns[c];
        float wc = d / fmaxf(sqrtf(nsq_i * nsq_c), 1e-8f);
        float q = nsq_i + nsq_c - 2.f * d + 2e-6f * (ns_i - ns_c) + 1.28e-10f;
        float we = sqrtf(fmaxf(q, 0.f));
        ac.x += wc * v.x; ac.y += wc * v.y; ac.z += wc * v.z; ac.w += wc * v.w;
        ae.x += we * v.x; ae.y += we * v.y; ae.z += we * v.z; ae.w += we * v.w;
    }
    float inv = 1.f / (float)max(t - s, 1);
    ((float4*)g_aggc)[(size_t)node * 32 + lane] =
        make_float4(ac.x * inv, ac.y * inv, ac.z * inv, ac.w * inv);
    ((float4*)g_agge)[(size_t)node * 32 + lane] =
        make_float4(ae.x * inv, ae.y * inv, ae.z * inv, ae.w * inv);
}

// ---------------- per-node stats of x3, x4 ----------------------------------------
__global__ void k_stats2(const float* __restrict__ x3, const float* __restrict__ x4) {
    int node = blockIdx.x * 8 + (threadIdx.x >> 5);
    if (node >= NN) return;
    int lane = threadIdx.x & 31;
    float4 a = ((const float4*)x3)[(size_t)node * 32 + lane];
    float4 b = ((const float4*)x4)[(size_t)node * 32 + lane];
    float s3  = a.x * a.x + a.y * a.y + a.z * a.z + a.w * a.w;
    float s4q = b.x * b.x + b.y * b.y + b.z * b.z + b.w * b.w;
    float s4s = b.x + b.y + b.z + b.w;
    s3 = wredsum(s3); s4q = wredsum(s4q); s4s = wredsum(s4s);
    if (lane == 0) { g_n3sq[node] = s3; g_n4sq[node] = s4q; g_s4[node] = s4s; }
}

// ---------------- fused layer-2 edge weights + aggregation ------------------------
__global__ void k_agg2(const float* __restrict__ x3, const float* __restrict__ x4) {
    int node = blockIdx.x * 8 + (threadIdx.x >> 5);
    if (node >= NN) return;
    int lane = threadIdx.x & 31;
    const float4* x3b = (const float4*)x3;
    const float4* x4b = (const float4*)x4;
    float4 a3 = x3b[(size_t)node * 32 + lane];
    float4 a4 = x4b[(size_t)node * 32 + lane];
    float n3i = g_n3sq[node], n4i = g_n4sq[node], s4i = g_s4[node];
    int s = g_rowptr[node], t = g_rowptr[node + 1];
    float4 ac = make_float4(0.f, 0.f, 0.f, 0.f);
    float4 ae = make_float4(0.f, 0.f, 0.f, 0.f);
    for (int j = s; j < t; j++) {
        int c = g_csr[j];
        float4 v3 = x3b[(size_t)c * 32 + lane];
        float4 v4 = x4b[(size_t)c * 32 + lane];
        float d3 = a3.x * v3.x + a3.y * v3.y + a3.z * v3.z + a3.w * v3.w;
        float d4 = a4.x * v4.x + a4.y * v4.y + a4.z * v4.z + a4.w * v4.w;
        d3 = wredsum(d3);
        d4 = wredsum(d4);
        float wc = d3 / fmaxf(sqrtf(n3i * g_n3sq[c]), 1e-8f);
        float q = n4i + g_n4sq[c] - 2.f * d4 + 2e-6f * (s4i - g_s4[c]) + 1.28e-10f;
        float we = sqrtf(fmaxf(q, 0.f));
        ac.x += wc * v3.x; ac.y += wc * v3.y; ac.z += wc * v3.z; ac.w += wc * v3.w;
        ae.x += we * v4.x; ae.y += we * v4.y; ae.z += we * v4.z; ae.w += we * v4.w;
    }
    float inv = 1.f / (float)max(t - s, 1);
    ((float4*)g_aggc)[(size_t)node * 32 + lane] =
        make_float4(ac.x * inv, ac.y * inv, ac.z * inv, ac.w * inv);
    ((float4*)g_agge)[(size_t)node * 32 + lane] =
        make_float4(ae.x * inv, ae.y * inv, ae.z * inv, ae.w * inv);
}

// ---------------- weight prep: transpose + bf16 split -----------------------------
// out[n*KT + k] = split of W[k, n]; k<128 from Wa, else from Wb (k-128).
__global__ void k_prepW(const float* __restrict__ Wa, const float* __restrict__ Wb,
                        __nv_bfloat16* __restrict__ oh, __nv_bfloat16* __restrict__ ol,
                        int BNw, int KT) {
    int i = blockIdx.x * blockDim.x + threadIdx.x;
    if (i >= BNw * KT) return;
    int n = i / KT, k = i % KT;
    float v = (k < 128) ? Wa[(size_t)k * BNw + n] : Wb[(size_t)(k - 128) * BNw + n];
    __nv_bfloat16 h = __float2bfloat16(v);
    oh[i] = h;
    ol[i] = __float2bfloat16(v - __bfloat162float(h));
}

// ---------------- mma helpers ------------------------------------------------------
__device__ __forceinline__ void ldm_x4(uint32_t* r, uint32_t addr) {
    asm volatile("ldmatrix.sync.aligned.m8n8.x4.shared.b16 {%0,%1,%2,%3}, [%4];"
                 : "=r"(r[0]), "=r"(r[1]), "=r"(r[2]), "=r"(r[3]) : "r"(addr));
}
__device__ __forceinline__ void mma_bf16(float* c, const uint32_t* a, const uint32_t* b) {
    asm volatile(
        "mma.sync.aligned.m16n8k16.row.col.f32.bf16.bf16.f32 "
        "{%0,%1,%2,%3}, {%4,%5,%6,%7}, {%8,%9}, {%0,%1,%2,%3};"
        : "+f"(c[0]), "+f"(c[1]), "+f"(c[2]), "+f"(c[3])
        : "r"(a[0]), "r"(a[1]), "r"(a[2]), "r"(a[3]), "r"(b[0]), "r"(b[1]));
}
__device__ __forceinline__ uint32_t pack_bf16(float a, float b) {
    __nv_bfloat16 h0 = __float2bfloat16(a);
    __nv_bfloat16 h1 = __float2bfloat16(b);
    return (uint32_t)__bfloat16_as_ushort(h0) | ((uint32_t)__bfloat16_as_ushort(h1) << 16);
}

// ---------------- split-bf16 tensor-core GEMM (legacy mma.sync path) ---------------
// C[M,BN] = act( [A1 | A2] @ Wt^T + bias ),  Wt: [BN, KT] bf16 hi/lo row-major.
// ACT: 0 none, 1 relu, 2 tanh. BM=128, 8 warps as 4(m) x 2(n).
template <int BN, int KT, int ACT>
__global__ __launch_bounds__(256, 2) void k_mma_gemm(
    const float* __restrict__ A1, const float* __restrict__ A2,
    const __nv_bfloat16* __restrict__ Bhg, const __nv_bfloat16* __restrict__ Blg,
    const float* __restrict__ bias, float* __restrict__ Cout, int M) {
    constexpr int BK = 32;        // bf16 k per chunk
    constexpr int PITCH = 40;     // bf16 elems per smem row (80B: conflict-free ldmatrix)
    constexpr int NT = BN / 16;   // n8-tiles per warp (warp spans BN/2 cols)

    __shared__ __nv_bfloat16 sAh[128 * PITCH];
    __shared__ __nv_bfloat16 sAl[128 * PITCH];
    __shared__ __nv_bfloat16 sBh[BN * PITCH];
    __shared__ __nv_bfloat16 sBl[BN * PITCH];

    int tid = threadIdx.x, wid = tid >> 5, lane = tid & 31;
    int wm = (wid >> 1) * 32;
    int wn = (wid & 1) * (BN / 2);
    int m0 = blockIdx.x * 128;

    float acc[2][NT][4];
#pragma unroll
    for (int i = 0; i < 2; i++)
#pragma unroll
        for (int j = 0; j < NT; j++)
#pragma unroll
            for (int q = 0; q < 4; q++) acc[i][j][q] = 0.f;

    // precompute ldmatrix lane addresses (row parts)
    int aRow = lane & 15;               // A: row within 16-row tile
    int aColSel = (lane >> 4) * 8;      // A: +8 cols for lanes 16-31
    int bRow = (lane & 7) + ((lane >> 4) << 3);  // B: n row offset within 16
    int bColSel = ((lane >> 3) & 1) * 8;         // B: +8 cols for odd groups

    for (int kc = 0; kc < KT / BK; kc++) {
        int k0 = kc * BK;
        const float* As;
        int kA;
        if (KT == 256) { As = (k0 < 128) ? A1 : A2; kA = k0 & 127; }
        else           { As = A1; kA = k0; }

        // --- A chunk: 128 rows x 32 fp32 -> hi/lo bf16 ---
        {
            int r = tid >> 1, h = (tid & 1) * 16;
            int m = m0 + r;
            float4 f0, f1, f2, f3;
            if (m < M) {
                const float* s = As + (size_t)m * CD + kA + h;
                f0 = *(const float4*)(s);
                f1 = *(const float4*)(s + 4);
                f2 = *(const float4*)(s + 8);
                f3 = *(const float4*)(s + 12);
            } else {
                f0 = make_float4(0.f, 0.f, 0.f, 0.f);
                f1 = f0; f2 = f0; f3 = f0;
            }
            float fv[16] = {f0.x, f0.y, f0.z, f0.w, f1.x, f1.y, f1.z, f1.w,
                            f2.x, f2.y, f2.z, f2.w, f3.x, f3.y, f3.z, f3.w};
            uint32_t hw[8], lw[8];
#pragma unroll
            for (int j = 0; j < 8; j++) {
                float a = fv[2 * j], b = fv[2 * j + 1];
                hw[j] = pack_bf16(a, b);
                float ra = a - __bfloat162float(__ushort_as_bfloat16((uint16_t)hw[j]));
                float rb = b - __bfloat162float(__ushort_as_bfloat16((uint16_t)(hw[j] >> 16)));
                lw[j] = pack_bf16(ra, rb);
            }
            uint32_t off = (uint32_t)(r * PITCH + h);
            *(uint4*)(sAh + off)     = make_uint4(hw[0], hw[1], hw[2], hw[3]);
            *(uint4*)(sAh + off + 8) = make_uint4(hw[4], hw[5], hw[6], hw[7]);
            *(uint4*)(sAl + off)     = make_uint4(lw[0], lw[1], lw[2], lw[3]);
            *(uint4*)(sAl + off + 8) = make_uint4(lw[4], lw[5], lw[6], lw[7]);
        }
        // --- B chunk: BN rows x 32 bf16 (pre-split in global) ---
        if (tid < BN * 2) {
            int n = tid >> 1, h = (tid & 1) * 16;
            const __nv_bfloat16* gh = Bhg + (size_t)n * KT + k0 + h;
            const __nv_bfloat16* gl = Blg + (size_t)n * KT + k0 + h;
            uint4 vh0 = *(const uint4*)(gh);
            uint4 vh1 = *(const uint4*)(gh + 8);
            uint4 vl0 = *(const uint4*)(gl);
            uint4 vl1 = *(const uint4*)(gl + 8);
            uint32_t off = (uint32_t)(n * PITCH + h);
            *(uint4*)(sBh + off)     = vh0;
            *(uint4*)(sBh + off + 8) = vh1;
            *(uint4*)(sBl + off)     = vl0;
            *(uint4*)(sBl + off + 8) = vl1;
        }
        __syncthreads();

#pragma unroll
        for (int kk = 0; kk < 2; kk++) {
            int kb = kk * 16;
            uint32_t ah[2][4], al[2][4];
#pragma unroll
            for (int mt = 0; mt < 2; mt++) {
                uint32_t offA = (uint32_t)((wm + mt * 16 + aRow) * PITCH + kb + aColSel) * 2;
                ldm_x4(ah[mt], smem_u32(sAh) + offA);
                ldm_x4(al[mt], smem_u32(sAl) + offA);
            }
#pragma unroll
            for (int nt2 = 0; nt2 < NT / 2; nt2++) {
                int nb = wn + nt2 * 16;
                uint32_t offB = (uint32_t)((nb + bRow) * PITCH + kb + bColSel) * 2;
                uint32_t bh[4], bl[4];
                ldm_x4(bh, smem_u32(sBh) + offB);
                ldm_x4(bl, smem_u32(sBl) + offB);
#pragma unroll
                for (int half = 0; half < 2; half++) {
                    uint32_t bhp[2] = {bh[half * 2], bh[half * 2 + 1]};
                    uint32_t blp[2] = {bl[half * 2], bl[half * 2 + 1]};
                    int nt = nt2 * 2 + half;
#pragma unroll
                    for (int mt = 0; mt < 2; mt++) {
                        mma_bf16(acc[mt][nt], ah[mt], bhp);   // Ah*Bh
                        mma_bf16(acc[mt][nt], ah[mt], blp);   // Ah*Bl
                        mma_bf16(acc[mt][nt], al[mt], bhp);   // Al*Bh
                    }
                }
            }
        }
        __syncthreads();
    }

    // --- epilogue ---
#pragma unroll
    for (int mt = 0; mt < 2; mt++) {
#pragma unroll
        for (int nt = 0; nt < NT; nt++) {
            int col = wn + nt * 8 + (lane & 3) * 2;
            float b0 = __ldg(&bias[col]), b1 = __ldg(&bias[col + 1]);
#pragma unroll
            for (int rh = 0; rh < 2; rh++) {
                int m = m0 + wm + mt * 16 + (lane >> 2) + rh * 8;
                if (m < M) {
                    float v0 = acc[mt][nt][rh * 2 + 0] + b0;
                    float v1 = acc[mt][nt][rh * 2 + 1] + b1;
                    if (ACT == 1) { v0 = fmaxf(v0, 0.f); v1 = fmaxf(v1, 0.f); }
                    if (ACT == 2) {
                        asm("tanh.approx.f32 %0, %0;" : "+f"(v0));
                        asm("tanh.approx.f32 %0, %0;" : "+f"(v1));
                    }
                    *(float2*)(Cout + (size_t)m * BN + col) = make_float2(v0, v1);
                }
            }
        }
    }
}

// ---------------- attention pooling (warp per node) -------------------------------
__global__ void k_pool(const float* __restrict__ x3, const float* __restrict__ x4,
                       const float* __restrict__ attW2, float* __restrict__ emb) {
    int node = blockIdx.x * 8 + (threadIdx.x >> 5);
    if (node >= NN) return;
    int lane = threadIdx.x & 31;
    float w2a = attW2[lane], w2b = attW2[lane + 32];
    float wk[4];
#pragma unroll
    for (int k = 0; k < 4; k++) {
        const float* H = g_h + (size_t)k * NN * AH + (size_t)node * AH;
        float p = H[lane] * w2a + H[lane + 32] * w2b;
        wk[k] = wredsum(p);
    }
    float m = fmaxf(fmaxf(wk[0], wk[1]), fmaxf(wk[2], wk[3]));
    float e0 = __expf(wk[0] - m), e1 = __expf(wk[1] - m);
    float e2 = __expf(wk[2] - m), e3 = __expf(wk[3] - m);
    float inv = 1.f / (e0 + e1 + e2 + e3);
    float b0 = e0 * inv, b1 = e1 * inv, b2 = e2 * inv, b3 = e3 * inv;
    float4 v1 = ((const float4*)g_x1)[(size_t)node * 32 + lane];
    float4 v2 = ((const float4*)g_x2)[(size_t)node * 32 + lane];
    float4 v3 = ((const float4*)x3)[(size_t)node * 32 + lane];
    float4 v4 = ((const float4*)x4)[(size_t)node * 32 + lane];
    float4 r;
    r.x = b0 * v1.x + b1 * v2.x + b2 * v3.x + b3 * v4.x;
    r.y = b0 * v1.y + b1 * v2.y + b2 * v3.y + b3 * v4.y;
    r.z = b0 * v1.z + b1 * v2.z + b2 * v3.z + b3 * v4.z;
    r.w = b0 * v1.w + b1 * v2.w + b2 * v3.w + b3 * v4.w;
    ((float4*)emb)[(size_t)node * 32 + lane] = r;
}

// ---------------- host ------------------------------------------------------------
extern "C" void kernel_launch(void* const* d_in, const int* in_sizes, int n_in,
                              void* d_out, int out_size) {
    const float* x     = (const float*)d_in[0];
    const int*   row   = (const int*)d_in[1];
    const int*   col   = (const int*)d_in[2];
    const float* Wl0   = (const float*)d_in[3];
    const float* bl0   = (const float*)d_in[4];
    const float* Wr0   = (const float*)d_in[5];
    const float* Wl1   = (const float*)d_in[6];
    const float* bl1   = (const float*)d_in[7];
    const float* Wr1   = (const float*)d_in[8];
    const float* attW1 = (const float*)d_in[9];
    const float* attb1 = (const float*)d_in[10];
    const float* attW2 = (const float*)d_in[11];

    float* out = (float*)d_out;
    float* emb = out;
    float* x3  = out + (size_t)NN * CD;
    float* x4  = out + (size_t)2 * NN * CD;

    void *pdeg, *pcur;
    float *aggc, *agge, *x1b, *x2b, *hbuf;
    __nv_bfloat16 *w0h, *w0l, *w1h, *w1l, *wah, *wal;
    cudaGetSymbolAddress(&pdeg, g_deg);
    cudaGetSymbolAddress(&pcur, g_cursor);
    cudaGetSymbolAddress((void**)&aggc, g_aggc);
    cudaGetSymbolAddress((void**)&agge, g_agge);
    cudaGetSymbolAddress((void**)&x1b, g_x1);
    cudaGetSymbolAddress((void**)&x2b, g_x2);
    cudaGetSymbolAddress((void**)&hbuf, g_h);
    cudaGetSymbolAddress((void**)&w0h, g_w0h);
    cudaGetSymbolAddress((void**)&w0l, g_w0l);
    cudaGetSymbolAddress((void**)&w1h, g_w1h);
    cudaGetSymbolAddress((void**)&w1l, g_w1l);
    cudaGetSymbolAddress((void**)&wah, g_wah);
    cudaGetSymbolAddress((void**)&wal, g_wal);

    cudaMemsetAsync(pdeg, 0, NN * sizeof(int));
    cudaMemsetAsync(pcur, 0, NN * sizeof(int));

    const int nodeBlocks = (NN + 7) / 8;
    const int edgeBlocks = (NE + 255) / 256;
    const int TG = (NN + 127) / 128;  // 391 GEMM tiles

    // weight prep (independent of graph data)
    k_prepW<<<(128 * 256 + 255) / 256, 256>>>(Wl0, Wr0, w0h, w0l, 128, 256);
    k_prepW<<<(128 * 256 + 255) / 256, 256>>>(Wl1, Wr1, w1h, w1l, 128, 256);
    k_prepW<<<(64 * 128 + 255) / 256, 256>>>(attW1, attW1, wah, wal, 64, 128);

    k_stats1<<<nodeBlocks, 256>>>(x);
    k_deg<<<edgeBlocks, 256>>>(row);
    k_scan<<<1, 1024>>>();
    k_scatter<<<edgeBlocks, 256>>>(row, col);
    k_agg1<<<nodeBlocks, 256>>>(x);

    // layer 1: x3 = relu([aggc|x]@W0 + bl0), x4 = relu([agge|x]@W0 + bl0)
    k_mma_gemm<128, 256, 1><<<TG, 256>>>(aggc, x, w0h, w0l, bl0, x3, NN);
    k_mma_gemm<128, 256, 1><<<TG, 256>>>(agge, x, w0h, w0l, bl0, x4, NN);

    k_stats2<<<nodeBlocks, 256>>>(x3, x4);
    k_agg2<<<nodeBlocks, 256>>>(x3, x4);

    // layer 2
    k_mma_gemm<128, 256, 0><<<TG, 256>>>(aggc, x3, w1h, w1l, bl1, x1b, NN);
    k_mma_gemm<128, 256, 0><<<TG, 256>>>(agge, x4, w1h, w1l, bl1, x2b, NN);

    // attention projections: H_k = tanh(X_k @ attW1 + attb1)
    k_mma_gemm<64, 128, 2><<<TG, 256>>>(x1b, nullptr, wah, wal, attb1,
                                        hbuf + (size_t)0 * NN * AH, NN);
    k_mma_gemm<64, 128, 2><<<TG, 256>>>(x2b, nullptr, wah, wal, attb1,
                                        hbuf + (size_t)1 * NN * AH, NN);
    k_mma_gemm<64, 128, 2><<<TG, 256>>>(x3, nullptr, wah, wal, attb1,
                                        hbuf + (size_t)2 * NN * AH, NN);
    k_mma_gemm<64, 128, 2><<<TG, 256>>>(x4, nullptr, wah, wal, attb1,
                                        hbuf + (size_t)3 * NN * AH, NN);

    k_pool<<<nodeBlocks, 256>>>(x3, x4, attW2, emb);
}

// round 6
// speedup vs baseline: 1.3469x; 1.0781x over previous
#include <cuda_runtime.h>
#include <cuda_bf16.h>
#include <math.h>
#include <stdint.h>

#define NN 50000
#define NE 800000
#define CD 128
#define AH 64

// ---------------- scratch (static device globals) ---------------------------------
__device__ float g_nsq[NN];
__device__ float g_ns[NN];
__device__ float g_n3sq[NN];
__device__ float g_n4sq[NN];
__device__ float g_s4[NN];
__device__ int   g_deg[NN];
__device__ int   g_rowptr[NN + 1];
__device__ int   g_cursor[NN];
__device__ int   g_csr[NE];
__device__ float g_aggc[(size_t)NN * CD];
__device__ float g_agge[(size_t)NN * CD];
__device__ float g_x1[(size_t)NN * CD];
__device__ float g_x2[(size_t)NN * CD];
__device__ float g_h[(size_t)4 * NN * AH];
// split-bf16 transposed weights: [N rows x K cols]
__device__ __nv_bfloat16 g_w0h[128 * 256];
__device__ __nv_bfloat16 g_w0l[128 * 256];
__device__ __nv_bfloat16 g_w1h[128 * 256];
__device__ __nv_bfloat16 g_w1l[128 * 256];
__device__ __nv_bfloat16 g_wah[64 * 128];
__device__ __nv_bfloat16 g_wal[64 * 128];

__device__ __forceinline__ uint32_t smem_u32(const void* p) {
    uint32_t a;
    asm("{ .reg .u64 t; cvta.to.shared.u64 t, %1; cvt.u32.u64 %0, t; }" : "=r"(a) : "l"(p));
    return a;
}

__device__ __forceinline__ float wredsum(float v) {
#pragma unroll
    for (int o = 16; o; o >>= 1) v += __shfl_xor_sync(0xffffffffu, v, o);
    return v;
}
// reduce within each 16-lane half
__device__ __forceinline__ float hredsum(float v) {
#pragma unroll
    for (int o = 8; o; o >>= 1) v += __shfl_xor_sync(0xffffffffu, v, o);
    return v;
}

// ---------------- per-node stats of x ---------------------------------------------
__global__ void k_stats1(const float* __restrict__ x) {
    int node = blockIdx.x * 8 + (threadIdx.x >> 5);
    if (node >= NN) return;
    int lane = threadIdx.x & 31;
    float4 v = *(const float4*)(x + (size_t)node * CD + lane * 4);
    float sq = v.x * v.x + v.y * v.y + v.z * v.z + v.w * v.w;
    float s  = v.x + v.y + v.z + v.w;
    sq = wredsum(sq);
    s  = wredsum(s);
    if (lane == 0) { g_nsq[node] = sq; g_ns[node] = s; }
}

// ---------------- CSR build -------------------------------------------------------
__global__ void k_deg(const int* __restrict__ row) {
    int e = blockIdx.x * blockDim.x + threadIdx.x;
    if (e < NE) atomicAdd(&g_deg[row[e]], 1);
}

// 1024 threads, thread-serial segments + warp-shuffle block scan (3 syncs total)
__global__ void k_scan() {
    const int PER = (NN + 1023) / 1024;  // 49
    int tid = threadIdx.x;
    int t0 = tid * PER;
    int sum = 0;
    for (int i = 0; i < PER; i++) {
        int idx = t0 + i;
        if (idx < NN) sum += g_deg[idx];
    }
    int lane = tid & 31, wid = tid >> 5;
    int v = sum;
#pragma unroll
    for (int o = 1; o < 32; o <<= 1) {
        int t = __shfl_up_sync(0xffffffffu, v, o);
        if (lane >= o) v += t;
    }
    __shared__ int wsum[32];
    if (lane == 31) wsum[wid] = v;
    __syncthreads();
    if (wid == 0) {
        int w = wsum[lane];
#pragma unroll
        for (int o = 1; o < 32; o <<= 1) {
            int t = __shfl_up_sync(0xffffffffu, w, o);
            if (lane >= o) w += t;
        }
        wsum[lane] = w;
    }
    __syncthreads();
    int offset = v - sum + (wid ? wsum[wid - 1] : 0);
    int run = offset;
    for (int i = 0; i < PER; i++) {
        int idx = t0 + i;
        if (idx < NN) { g_rowptr[idx] = run; run += g_deg[idx]; }
    }
    if (t0 < NN && t0 + PER >= NN) g_rowptr[NN] = run;
}

__global__ void k_scatter(const int* __restrict__ row, const int* __restrict__ col) {
    int e = blockIdx.x * blockDim.x + threadIdx.x;
    if (e >= NE) return;
    int r = row[e];
    int p = atomicAdd(&g_cursor[r], 1);
    g_csr[g_rowptr[r] + p] = col[e];
}

// ---------------- fused layer-1 agg: warp per node, half-warp per edge -------------
__global__ void k_agg1(const float* __restrict__ x) {
    int node = blockIdx.x * 8 + (threadIdx.x >> 5);
    if (node >= NN) return;
    int lane = threadIdx.x & 31;
    int half = lane >> 4, sub = lane & 15;
    const float4* xb = (const float4*)x;
    float4 xi0 = xb[(size_t)node * 32 + sub * 2];
    float4 xi1 = xb[(size_t)node * 32 + sub * 2 + 1];
    float nsq_i = g_nsq[node], ns_i = g_ns[node];
    int s = g_rowptr[node], t = g_rowptr[node + 1];
    float ac[8] = {0.f, 0.f, 0.f, 0.f, 0.f, 0.f, 0.f, 0.f};
    float ae[8] = {0.f, 0.f, 0.f, 0.f, 0.f, 0.f, 0.f, 0.f};
    for (int base = s; base < t; base += 2) {
        int j = base + half;
        bool ok = j < t;
        int c = ok ? __ldg(&g_csr[j]) : node;
        float4 v0 = xb[(size_t)c * 32 + sub * 2];
        float4 v1 = xb[(size_t)c * 32 + sub * 2 + 1];
        float d = xi0.x * v0.x + xi0.y * v0.y + xi0.z * v0.z + xi0.w * v0.w
                + xi1.x * v1.x + xi1.y * v1.y + xi1.z * v1.z + xi1.w * v1.w;
        d = hredsum(d);
        float nsqc = g_nsq[c], nsc = g_ns[c];
        float wc = d / fmaxf(sqrtf(nsq_i * nsqc), 1e-8f);
        float q = nsq_i + nsqc - 2.f * d + 2e-6f * (ns_i - nsc) + 1.28e-10f;
        float we = sqrtf(fmaxf(q, 0.f));
        if (!ok) { wc = 0.f; we = 0.f; }
        ac[0] += wc * v0.x; ac[1] += wc * v0.y; ac[2] += wc * v0.z; ac[3] += wc * v0.w;
        ac[4] += wc * v1.x; ac[5] += wc * v1.y; ac[6] += wc * v1.z; ac[7] += wc * v1.w;
        ae[0] += we * v0.x; ae[1] += we * v0.y; ae[2] += we * v0.z; ae[3] += we * v0.w;
        ae[4] += we * v1.x; ae[5] += we * v1.y; ae[6] += we * v1.z; ae[7] += we * v1.w;
    }
#pragma unroll
    for (int i = 0; i < 8; i++) {
        ac[i] += __shfl_xor_sync(0xffffffffu, ac[i], 16);
        ae[i] += __shfl_xor_sync(0xffffffffu, ae[i], 16);
    }
    float inv = 1.f / (float)max(t - s, 1);
    int fidx = node * 32 + sub * 2 + half;
    int b = half * 4;
    ((float4*)g_aggc)[fidx] =
        make_float4(ac[b] * inv, ac[b + 1] * inv, ac[b + 2] * inv, ac[b + 3] * inv);
    ((float4*)g_agge)[fidx] =
        make_float4(ae[b] * inv, ae[b + 1] * inv, ae[b + 2] * inv, ae[b + 3] * inv);
}

// ---------------- per-node stats of x3, x4 ----------------------------------------
__global__ void k_stats2(const float* __restrict__ x3, const float* __restrict__ x4) {
    int node = blockIdx.x * 8 + (threadIdx.x >> 5);
    if (node >= NN) return;
    int lane = threadIdx.x & 31;
    float4 a = ((const float4*)x3)[(size_t)node * 32 + lane];
    float4 b = ((const float4*)x4)[(size_t)node * 32 + lane];
    float s3  = a.x * a.x + a.y * a.y + a.z * a.z + a.w * a.w;
    float s4q = b.x * b.x + b.y * b.y + b.z * b.z + b.w * b.w;
    float s4s = b.x + b.y + b.z + b.w;
    s3 = wredsum(s3); s4q = wredsum(s4q); s4s = wredsum(s4s);
    if (lane == 0) { g_n3sq[node] = s3; g_n4sq[node] = s4q; g_s4[node] = s4s; }
}

// ---------------- fused layer-2 agg: warp per node, half-warp per edge -------------
__global__ void k_agg2(const float* __restrict__ x3, const float* __restrict__ x4) {
    int node = blockIdx.x * 8 + (threadIdx.x >> 5);
    if (node >= NN) return;
    int lane = threadIdx.x & 31;
    int half = lane >> 4, sub = lane & 15;
    const float4* x3b = (const float4*)x3;
    const float4* x4b = (const float4*)x4;
    float4 a30 = x3b[(size_t)node * 32 + sub * 2];
    float4 a31 = x3b[(size_t)node * 32 + sub * 2 + 1];
    float4 a40 = x4b[(size_t)node * 32 + sub * 2];
    float4 a41 = x4b[(size_t)node * 32 + sub * 2 + 1];
    float n3i = g_n3sq[node], n4i = g_n4sq[node], s4i = g_s4[node];
    int s = g_rowptr[node], t = g_rowptr[node + 1];
    float ac[8] = {0.f, 0.f, 0.f, 0.f, 0.f, 0.f, 0.f, 0.f};
    float ae[8] = {0.f, 0.f, 0.f, 0.f, 0.f, 0.f, 0.f, 0.f};
    for (int base = s; base < t; base += 2) {
        int j = base + half;
        bool ok = j < t;
        int c = ok ? __ldg(&g_csr[j]) : node;
        float4 v30 = x3b[(size_t)c * 32 + sub * 2];
        float4 v31 = x3b[(size_t)c * 32 + sub * 2 + 1];
        float4 v40 = x4b[(size_t)c * 32 + sub * 2];
        float4 v41 = x4b[(size_t)c * 32 + sub * 2 + 1];
        float d3 = a30.x * v30.x + a30.y * v30.y + a30.z * v30.z + a30.w * v30.w
                 + a31.x * v31.x + a31.y * v31.y + a31.z * v31.z + a31.w * v31.w;
        float d4 = a40.x * v40.x + a40.y * v40.y + a40.z * v40.z + a40.w * v40.w
                 + a41.x * v41.x + a41.y * v41.y + a41.z * v41.z + a41.w * v41.w;
#pragma unroll
        for (int o = 8; o; o >>= 1) {
            d3 += __shfl_xor_sync(0xffffffffu, d3, o);
            d4 += __shfl_xor_sync(0xffffffffu, d4, o);
        }
        float wc = d3 / fmaxf(sqrtf(n3i * g_n3sq[c]), 1e-8f);
        float q = n4i + g_n4sq[c] - 2.f * d4 + 2e-6f * (s4i - g_s4[c]) + 1.28e-10f;
        float we = sqrtf(fmaxf(q, 0.f));
        if (!ok) { wc = 0.f; we = 0.f; }
        ac[0] += wc * v30.x; ac[1] += wc * v30.y; ac[2] += wc * v30.z; ac[3] += wc * v30.w;
        ac[4] += wc * v31.x; ac[5] += wc * v31.y; ac[6] += wc * v31.z; ac[7] += wc * v31.w;
        ae[0] += we * v40.x; ae[1] += we * v40.y; ae[2] += we * v40.z; ae[3] += we * v40.w;
        ae[4] += we * v41.x; ae[5] += we * v41.y; ae[6] += we * v41.z; ae[7] += we * v41.w;
    }
#pragma unroll
    for (int i = 0; i < 8; i++) {
        ac[i] += __shfl_xor_sync(0xffffffffu, ac[i], 16);
        ae[i] += __shfl_xor_sync(0xffffffffu, ae[i], 16);
    }
    float inv = 1.f / (float)max(t - s, 1);
    int fidx = node * 32 + sub * 2 + half;
    int b = half * 4;
    ((float4*)g_aggc)[fidx] =
        make_float4(ac[b] * inv, ac[b + 1] * inv, ac[b + 2] * inv, ac[b + 3] * inv);
    ((float4*)g_agge)[fidx] =
        make_float4(ae[b] * inv, ae[b + 1] * inv, ae[b + 2] * inv, ae[b + 3] * inv);
}

// ---------------- weight prep: transpose + bf16 split -----------------------------
__global__ void k_prepW(const float* __restrict__ Wa, const float* __restrict__ Wb,
                        __nv_bfloat16* __restrict__ oh, __nv_bfloat16* __restrict__ ol,
                        int BNw, int KT) {
    int i = blockIdx.x * blockDim.x + threadIdx.x;
    if (i >= BNw * KT) return;
    int n = i / KT, k = i % KT;
    float v = (k < 128) ? Wa[(size_t)k * BNw + n] : Wb[(size_t)(k - 128) * BNw + n];
    __nv_bfloat16 h = __float2bfloat16(v);
    oh[i] = h;
    ol[i] = __float2bfloat16(v - __bfloat162float(h));
}

// ---------------- mma helpers ------------------------------------------------------
__device__ __forceinline__ void ldm_x4(uint32_t* r, uint32_t addr) {
    asm volatile("ldmatrix.sync.aligned.m8n8.x4.shared.b16 {%0,%1,%2,%3}, [%4];"
                 : "=r"(r[0]), "=r"(r[1]), "=r"(r[2]), "=r"(r[3]) : "r"(addr));
}
__device__ __forceinline__ void mma_bf16(float* c, const uint32_t* a, const uint32_t* b) {
    asm volatile(
        "mma.sync.aligned.m16n8k16.row.col.f32.bf16.bf16.f32 "
        "{%0,%1,%2,%3}, {%4,%5,%6,%7}, {%8,%9}, {%0,%1,%2,%3};"
        : "+f"(c[0]), "+f"(c[1]), "+f"(c[2]), "+f"(c[3])
        : "r"(a[0]), "r"(a[1]), "r"(a[2]), "r"(a[3]), "r"(b[0]), "r"(b[1]));
}
__device__ __forceinline__ uint32_t pack_bf16(float a, float b) {
    __nv_bfloat16 h0 = __float2bfloat16(a);
    __nv_bfloat16 h1 = __float2bfloat16(b);
    return (uint32_t)__bfloat16_as_ushort(h0) | ((uint32_t)__bfloat16_as_ushort(h1) << 16);
}

// ---------------- split-bf16 tensor-core GEMM (legacy mma.sync path) ---------------
template <int BN, int KT, int ACT>
__global__ __launch_bounds__(256, 2) void k_mma_gemm(
    const float* __restrict__ A1, const float* __restrict__ A2,
    const __nv_bfloat16* __restrict__ Bhg, const __nv_bfloat16* __restrict__ Blg,
    const float* __restrict__ bias, float* __restrict__ Cout, int M) {
    constexpr int BK = 32;
    constexpr int PITCH = 40;
    constexpr int NT = BN / 16;

    __shared__ __nv_bfloat16 sAh[128 * PITCH];
    __shared__ __nv_bfloat16 sAl[128 * PITCH];
    __shared__ __nv_bfloat16 sBh[BN * PITCH];
    __shared__ __nv_bfloat16 sBl[BN * PITCH];

    int tid = threadIdx.x, wid = tid >> 5, lane = tid & 31;
    int wm = (wid >> 1) * 32;
    int wn = (wid & 1) * (BN / 2);
    int m0 = blockIdx.x * 128;

    float acc[2][NT][4];
#pragma unroll
    for (int i = 0; i < 2; i++)
#pragma unroll
        for (int j = 0; j < NT; j++)
#pragma unroll
            for (int q = 0; q < 4; q++) acc[i][j][q] = 0.f;

    int aRow = lane & 15;
    int aColSel = (lane >> 4) * 8;
    int bRow = (lane & 7) + ((lane >> 4) << 3);
    int bColSel = ((lane >> 3) & 1) * 8;

    for (int kc = 0; kc < KT / BK; kc++) {
        int k0 = kc * BK;
        const float* As;
        int kA;
        if (KT == 256) { As = (k0 < 128) ? A1 : A2; kA = k0 & 127; }
        else           { As = A1; kA = k0; }

        {
            int r = tid >> 1, h = (tid & 1) * 16;
            int m = m0 + r;
            float4 f0, f1, f2, f3;
            if (m < M) {
                const float* s = As + (size_t)m * CD + kA + h;
                f0 = *(const float4*)(s);
                f1 = *(const float4*)(s + 4);
                f2 = *(const float4*)(s + 8);
                f3 = *(const float4*)(s + 12);
            } else {
                f0 = make_float4(0.f, 0.f, 0.f, 0.f);
                f1 = f0; f2 = f0; f3 = f0;
            }
            float fv[16] = {f0.x, f0.y, f0.z, f0.w, f1.x, f1.y, f1.z, f1.w,
                            f2.x, f2.y, f2.z, f2.w, f3.x, f3.y, f3.z, f3.w};
            uint32_t hw[8], lw[8];
#pragma unroll
            for (int j = 0; j < 8; j++) {
                float a = fv[2 * j], b = fv[2 * j + 1];
                hw[j] = pack_bf16(a, b);
                float ra = a - __bfloat162float(__ushort_as_bfloat16((uint16_t)hw[j]));
                float rb = b - __bfloat162float(__ushort_as_bfloat16((uint16_t)(hw[j] >> 16)));
                lw[j] = pack_bf16(ra, rb);
            }
            uint32_t off = (uint32_t)(r * PITCH + h);
            *(uint4*)(sAh + off)     = make_uint4(hw[0], hw[1], hw[2], hw[3]);
            *(uint4*)(sAh + off + 8) = make_uint4(hw[4], hw[5], hw[6], hw[7]);
            *(uint4*)(sAl + off)     = make_uint4(lw[0], lw[1], lw[2], lw[3]);
            *(uint4*)(sAl + off + 8) = make_uint4(lw[4], lw[5], lw[6], lw[7]);
        }
        if (tid < BN * 2) {
            int n = tid >> 1, h = (tid & 1) * 16;
            const __nv_bfloat16* gh = Bhg + (size_t)n * KT + k0 + h;
            const __nv_bfloat16* gl = Blg + (size_t)n * KT + k0 + h;
            uint4 vh0 = *(const uint4*)(gh);
            uint4 vh1 = *(const uint4*)(gh + 8);
            uint4 vl0 = *(const uint4*)(gl);
            uint4 vl1 = *(const uint4*)(gl + 8);
            uint32_t off = (uint32_t)(n * PITCH + h);
            *(uint4*)(sBh + off)     = vh0;
            *(uint4*)(sBh + off + 8) = vh1;
            *(uint4*)(sBl + off)     = vl0;
            *(uint4*)(sBl + off + 8) = vl1;
        }
        __syncthreads();

#pragma unroll
        for (int kk = 0; kk < 2; kk++) {
            int kb = kk * 16;
            uint32_t ah[2][4], al[2][4];
#pragma unroll
            for (int mt = 0; mt < 2; mt++) {
                uint32_t offA = (uint32_t)((wm + mt * 16 + aRow) * PITCH + kb + aColSel) * 2;
                ldm_x4(ah[mt], smem_u32(sAh) + offA);
                ldm_x4(al[mt], smem_u32(sAl) + offA);
            }
#pragma unroll
            for (int nt2 = 0; nt2 < NT / 2; nt2++) {
                int nb = wn + nt2 * 16;
                uint32_t offB = (uint32_t)((nb + bRow) * PITCH + kb + bColSel) * 2;
                uint32_t bh[4], bl[4];
                ldm_x4(bh, smem_u32(sBh) + offB);
                ldm_x4(bl, smem_u32(sBl) + offB);
#pragma unroll
                for (int half = 0; half < 2; half++) {
                    uint32_t bhp[2] = {bh[half * 2], bh[half * 2 + 1]};
                    uint32_t blp[2] = {bl[half * 2], bl[half * 2 + 1]};
                    int nt = nt2 * 2 + half;
#pragma unroll
                    for (int mt = 0; mt < 2; mt++) {
                        mma_bf16(acc[mt][nt], ah[mt], bhp);
                        mma_bf16(acc[mt][nt], ah[mt], blp);
                        mma_bf16(acc[mt][nt], al[mt], bhp);
                    }
                }
            }
        }
        __syncthreads();
    }

#pragma unroll
    for (int mt = 0; mt < 2; mt++) {
#pragma unroll
        for (int nt = 0; nt < NT; nt++) {
            int col = wn + nt * 8 + (lane & 3) * 2;
            float b0 = __ldg(&bias[col]), b1 = __ldg(&bias[col + 1]);
#pragma unroll
            for (int rh = 0; rh < 2; rh++) {
                int m = m0 + wm + mt * 16 + (lane >> 2) + rh * 8;
                if (m < M) {
                    float v0 = acc[mt][nt][rh * 2 + 0] + b0;
                    float v1 = acc[mt][nt][rh * 2 + 1] + b1;
                    if (ACT == 1) { v0 = fmaxf(v0, 0.f); v1 = fmaxf(v1, 0.f); }
                    if (ACT == 2) {
                        asm("tanh.approx.f32 %0, %0;" : "+f"(v0));
                        asm("tanh.approx.f32 %0, %0;" : "+f"(v1));
                    }
                    *(float2*)(Cout + (size_t)m * BN + col) = make_float2(v0, v1);
                }
            }
        }
    }
}

// ---------------- attention pooling (warp per node) -------------------------------
__global__ void k_pool(const float* __restrict__ x3, const float* __restrict__ x4,
                       const float* __restrict__ attW2, float* __restrict__ emb) {
    int node = blockIdx.x * 8 + (threadIdx.x >> 5);
    if (node >= NN) return;
    int lane = threadIdx.x & 31;
    float w2a = attW2[lane], w2b = attW2[lane + 32];
    float wk[4];
#pragma unroll
    for (int k = 0; k < 4; k++) {
        const float* H = g_h + (size_t)k * NN * AH + (size_t)node * AH;
        float p = H[lane] * w2a + H[lane + 32] * w2b;
        wk[k] = wredsum(p);
    }
    float m = fmaxf(fmaxf(wk[0], wk[1]), fmaxf(wk[2], wk[3]));
    float e0 = __expf(wk[0] - m), e1 = __expf(wk[1] - m);
    float e2 = __expf(wk[2] - m), e3 = __expf(wk[3] - m);
    float inv = 1.f / (e0 + e1 + e2 + e3);
    float b0 = e0 * inv, b1 = e1 * inv, b2 = e2 * inv, b3 = e3 * inv;
    float4 v1 = ((const float4*)g_x1)[(size_t)node * 32 + lane];
    float4 v2 = ((const float4*)g_x2)[(size_t)node * 32 + lane];
    float4 v3 = ((const float4*)x3)[(size_t)node * 32 + lane];
    float4 v4 = ((const float4*)x4)[(size_t)node * 32 + lane];
    float4 r;
    r.x = b0 * v1.x + b1 * v2.x + b2 * v3.x + b3 * v4.x;
    r.y = b0 * v1.y + b1 * v2.y + b2 * v3.y + b3 * v4.y;
    r.z = b0 * v1.z + b1 * v2.z + b2 * v3.z + b3 * v4.z;
    r.w = b0 * v1.w + b1 * v2.w + b2 * v3.w + b3 * v4.w;
    ((float4*)emb)[(size_t)node * 32 + lane] = r;
}

// ---------------- host ------------------------------------------------------------
extern "C" void kernel_launch(void* const* d_in, const int* in_sizes, int n_in,
                              void* d_out, int out_size) {
    const float* x     = (const float*)d_in[0];
    const int*   row   = (const int*)d_in[1];
    const int*   col   = (const int*)d_in[2];
    const float* Wl0   = (const float*)d_in[3];
    const float* bl0   = (const float*)d_in[4];
    const float* Wr0   = (const float*)d_in[5];
    const float* Wl1   = (const float*)d_in[6];
    const float* bl1   = (const float*)d_in[7];
    const float* Wr1   = (const float*)d_in[8];
    const float* attW1 = (const float*)d_in[9];
    const float* attb1 = (const float*)d_in[10];
    const float* attW2 = (const float*)d_in[11];

    float* out = (float*)d_out;
    float* emb = out;
    float* x3  = out + (size_t)NN * CD;
    float* x4  = out + (size_t)2 * NN * CD;

    void *pdeg, *pcur;
    float *aggc, *agge, *x1b, *x2b, *hbuf;
    __nv_bfloat16 *w0h, *w0l, *w1h, *w1l, *wah, *wal;
    cudaGetSymbolAddress(&pdeg, g_deg);
    cudaGetSymbolAddress(&pcur, g_cursor);
    cudaGetSymbolAddress((void**)&aggc, g_aggc);
    cudaGetSymbolAddress((void**)&agge, g_agge);
    cudaGetSymbolAddress((void**)&x1b, g_x1);
    cudaGetSymbolAddress((void**)&x2b, g_x2);
    cudaGetSymbolAddress((void**)&hbuf, g_h);
    cudaGetSymbolAddress((void**)&w0h, g_w0h);
    cudaGetSymbolAddress((void**)&w0l, g_w0l);
    cudaGetSymbolAddress((void**)&w1h, g_w1h);
    cudaGetSymbolAddress((void**)&w1l, g_w1l);
    cudaGetSymbolAddress((void**)&wah, g_wah);
    cudaGetSymbolAddress((void**)&wal, g_wal);

    cudaMemsetAsync(pdeg, 0, NN * sizeof(int));
    cudaMemsetAsync(pcur, 0, NN * sizeof(int));

    const int nodeBlocks = (NN + 7) / 8;
    const int edgeBlocks = (NE + 255) / 256;
    const int TG = (NN + 127) / 128;

    k_prepW<<<(128 * 256 + 255) / 256, 256>>>(Wl0, Wr0, w0h, w0l, 128, 256);
    k_prepW<<<(128 * 256 + 255) / 256, 256>>>(Wl1, Wr1, w1h, w1l, 128, 256);
    k_prepW<<<(64 * 128 + 255) / 256, 256>>>(attW1, attW1, wah, wal, 64, 128);

    k_stats1<<<nodeBlocks, 256>>>(x);
    k_deg<<<edgeBlocks, 256>>>(row);
    k_scan<<<1, 1024>>>();
    k_scatter<<<edgeBlocks, 256>>>(row, col);
    k_agg1<<<nodeBlocks, 256>>>(x);

    k_mma_gemm<128, 256, 1><<<TG, 256>>>(aggc, x, w0h, w0l, bl0, x3, NN);
    k_mma_gemm<128, 256, 1><<<TG, 256>>>(agge, x, w0h, w0l, bl0, x4, NN);

    k_stats2<<<nodeBlocks, 256>>>(x3, x4);
    k_agg2<<<nodeBlocks, 256>>>(x3, x4);

    k_mma_gemm<128, 256, 0><<<TG, 256>>>(aggc, x3, w1h, w1l, bl1, x1b, NN);
    k_mma_gemm<128, 256, 0><<<TG, 256>>>(agge, x4, w1h, w1l, bl1, x2b, NN);

    k_mma_gemm<64, 128, 2><<<TG, 256>>>(x1b, nullptr, wah, wal, attb1,
                                        hbuf + (size_t)0 * NN * AH, NN);
    k_mma_gemm<64, 128, 2><<<TG, 256>>>(x2b, nullptr, wah, wal, attb1,
                                        hbuf + (size_t)1 * NN * AH, NN);
    k_mma_gemm<64, 128, 2><<<TG, 256>>>(x3, nullptr, wah, wal, attb1,
                                        hbuf + (size_t)2 * NN * AH, NN);
    k_mma_gemm<64, 128, 2><<<TG, 256>>>(x4, nullptr, wah, wal, attb1,
                                        hbuf + (size_t)3 * NN * AH, NN);

    k_pool<<<nodeBlocks, 256>>>(x3, x4, attW2, emb);
}

// round 7
// speedup vs baseline: 1.5762x; 1.1702x over previous
#include <cuda_runtime.h>
#include <cuda_bf16.h>
#include <math.h>
#include <stdint.h>

#define NN 50000
#define NE 800000
#define CD 128
#define AH 64

// ---------------- scratch (static device globals) ---------------------------------
__device__ float g_nsq[NN];
__device__ float g_ns[NN];
__device__ float g_n3sq[NN];
__device__ float g_n4sq[NN];
__device__ float g_s4[NN];
__device__ int   g_degcur[2 * NN];   // [0..NN) deg, [NN..2NN) cursor
__device__ int   g_rowptr[NN + 1];
__device__ int   g_csr[NE];
__device__ float g_aggc[(size_t)NN * CD];
__device__ float g_agge[(size_t)NN * CD];
__device__ float g_x1[(size_t)NN * CD];
__device__ float g_x2[(size_t)NN * CD];
__device__ float g_w[(size_t)NN * 4];    // attention logits [node][branch]
// split-bf16 transposed weights: [N rows x K cols]
__device__ __nv_bfloat16 g_w0h[128 * 256];
__device__ __nv_bfloat16 g_w0l[128 * 256];
__device__ __nv_bfloat16 g_w1h[128 * 256];
__device__ __nv_bfloat16 g_w1l[128 * 256];
__device__ __nv_bfloat16 g_wah[64 * 128];
__device__ __nv_bfloat16 g_wal[64 * 128];

struct GemmPtrs {
    const float* A1[4];
    const float* A2[4];
    float*       C[4];
};

__device__ __forceinline__ uint32_t smem_u32(const void* p) {
    uint32_t a;
    asm("{ .reg .u64 t; cvta.to.shared.u64 t, %1; cvt.u32.u64 %0, t; }" : "=r"(a) : "l"(p));
    return a;
}

__device__ __forceinline__ float wredsum(float v) {
#pragma unroll
    for (int o = 16; o; o >>= 1) v += __shfl_xor_sync(0xffffffffu, v, o);
    return v;
}
__device__ __forceinline__ float hredsum(float v) {
#pragma unroll
    for (int o = 8; o; o >>= 1) v += __shfl_xor_sync(0xffffffffu, v, o);
    return v;
}

// ---------------- per-node stats of x ---------------------------------------------
__global__ void k_stats1(const float* __restrict__ x) {
    int node = blockIdx.x * 8 + (threadIdx.x >> 5);
    if (node >= NN) return;
    int lane = threadIdx.x & 31;
    float4 v = *(const float4*)(x + (size_t)node * CD + lane * 4);
    float sq = v.x * v.x + v.y * v.y + v.z * v.z + v.w * v.w;
    float s  = v.x + v.y + v.z + v.w;
    sq = wredsum(sq);
    s  = wredsum(s);
    if (lane == 0) { g_nsq[node] = sq; g_ns[node] = s; }
}

// ---------------- CSR build -------------------------------------------------------
__global__ void k_deg(const int* __restrict__ row) {
    int e = blockIdx.x * blockDim.x + threadIdx.x;
    if (e < NE) atomicAdd(&g_degcur[row[e]], 1);
}

__global__ void k_scan() {
    const int PER = (NN + 1023) / 1024;
    int tid = threadIdx.x;
    int t0 = tid * PER;
    int sum = 0;
    for (int i = 0; i < PER; i++) {
        int idx = t0 + i;
        if (idx < NN) sum += g_degcur[idx];
    }
    int lane = tid & 31, wid = tid >> 5;
    int v = sum;
#pragma unroll
    for (int o = 1; o < 32; o <<= 1) {
        int t = __shfl_up_sync(0xffffffffu, v, o);
        if (lane >= o) v += t;
    }
    __shared__ int wsum[32];
    if (lane == 31) wsum[wid] = v;
    __syncthreads();
    if (wid == 0) {
        int w = wsum[lane];
#pragma unroll
        for (int o = 1; o < 32; o <<= 1) {
            int t = __shfl_up_sync(0xffffffffu, w, o);
            if (lane >= o) w += t;
        }
        wsum[lane] = w;
    }
    __syncthreads();
    int offset = v - sum + (wid ? wsum[wid - 1] : 0);
    int run = offset;
    for (int i = 0; i < PER; i++) {
        int idx = t0 + i;
        if (idx < NN) { g_rowptr[idx] = run; run += g_degcur[idx]; }
    }
    if (t0 < NN && t0 + PER >= NN) g_rowptr[NN] = run;
}

__global__ void k_scatter(const int* __restrict__ row, const int* __restrict__ col) {
    int e = blockIdx.x * blockDim.x + threadIdx.x;
    if (e >= NE) return;
    int r = row[e];
    int p = atomicAdd(&g_degcur[NN + r], 1);
    g_csr[g_rowptr[r] + p] = col[e];
}

// ---------------- fused layer-1 agg: warp/node, half-warp/edge, unroll 2 -----------
__global__ void k_agg1(const float* __restrict__ x) {
    int node = blockIdx.x * 8 + (threadIdx.x >> 5);
    if (node >= NN) return;
    int lane = threadIdx.x & 31;
    int half = lane >> 4, sub = lane & 15;
    const float4* xb = (const float4*)x;
    float4 xi0 = xb[(size_t)node * 32 + sub * 2];
    float4 xi1 = xb[(size_t)node * 32 + sub * 2 + 1];
    float nsq_i = g_nsq[node], ns_i = g_ns[node];
    int s = g_rowptr[node], t = g_rowptr[node + 1];
    float ac[8] = {0.f, 0.f, 0.f, 0.f, 0.f, 0.f, 0.f, 0.f};
    float ae[8] = {0.f, 0.f, 0.f, 0.f, 0.f, 0.f, 0.f, 0.f};
    for (int base = s; base < t; base += 4) {
        int jA = base + half, jB = base + 2 + half;
        bool okA = jA < t, okB = jB < t;
        int cA = okA ? __ldg(&g_csr[jA]) : node;
        int cB = okB ? __ldg(&g_csr[jB]) : node;
        float4 vA0 = xb[(size_t)cA * 32 + sub * 2];
        float4 vA1 = xb[(size_t)cA * 32 + sub * 2 + 1];
        float4 vB0 = xb[(size_t)cB * 32 + sub * 2];
        float4 vB1 = xb[(size_t)cB * 32 + sub * 2 + 1];
        float dA = xi0.x * vA0.x + xi0.y * vA0.y + xi0.z * vA0.z + xi0.w * vA0.w
                 + xi1.x * vA1.x + xi1.y * vA1.y + xi1.z * vA1.z + xi1.w * vA1.w;
        float dB = xi0.x * vB0.x + xi0.y * vB0.y + xi0.z * vB0.z + xi0.w * vB0.w
                 + xi1.x * vB1.x + xi1.y * vB1.y + xi1.z * vB1.z + xi1.w * vB1.w;
#pragma unroll
        for (int o = 8; o; o >>= 1) {
            dA += __shfl_xor_sync(0xffffffffu, dA, o);
            dB += __shfl_xor_sync(0xffffffffu, dB, o);
        }
        float nsqA = g_nsq[cA], nsA = g_ns[cA];
        float nsqB = g_nsq[cB], nsB = g_ns[cB];
        float wcA = dA / fmaxf(sqrtf(nsq_i * nsqA), 1e-8f);
        float qA = nsq_i + nsqA - 2.f * dA + 2e-6f * (ns_i - nsA) + 1.28e-10f;
        float weA = sqrtf(fmaxf(qA, 0.f));
        float wcB = dB / fmaxf(sqrtf(nsq_i * nsqB), 1e-8f);
        float qB = nsq_i + nsqB - 2.f * dB + 2e-6f * (ns_i - nsB) + 1.28e-10f;
        float weB = sqrtf(fmaxf(qB, 0.f));
        if (!okA) { wcA = 0.f; weA = 0.f; }
        if (!okB) { wcB = 0.f; weB = 0.f; }
        ac[0] += wcA * vA0.x + wcB * vB0.x; ac[1] += wcA * vA0.y + wcB * vB0.y;
        ac[2] += wcA * vA0.z + wcB * vB0.z; ac[3] += wcA * vA0.w + wcB * vB0.w;
        ac[4] += wcA * vA1.x + wcB * vB1.x; ac[5] += wcA * vA1.y + wcB * vB1.y;
        ac[6] += wcA * vA1.z + wcB * vB1.z; ac[7] += wcA * vA1.w + wcB * vB1.w;
        ae[0] += weA * vA0.x + weB * vB0.x; ae[1] += weA * vA0.y + weB * vB0.y;
        ae[2] += weA * vA0.z + weB * vB0.z; ae[3] += weA * vA0.w + weB * vB0.w;
        ae[4] += weA * vA1.x + weB * vB1.x; ae[5] += weA * vA1.y + weB * vB1.y;
        ae[6] += weA * vA1.z + weB * vB1.z; ae[7] += weA * vA1.w + weB * vB1.w;
    }
#pragma unroll
    for (int i = 0; i < 8; i++) {
        ac[i] += __shfl_xor_sync(0xffffffffu, ac[i], 16);
        ae[i] += __shfl_xor_sync(0xffffffffu, ae[i], 16);
    }
    float inv = 1.f / (float)max(t - s, 1);
    int fidx = node * 32 + sub * 2 + half;
    int b = half * 4;
    ((float4*)g_aggc)[fidx] =
        make_float4(ac[b] * inv, ac[b + 1] * inv, ac[b + 2] * inv, ac[b + 3] * inv);
    ((float4*)g_agge)[fidx] =
        make_float4(ae[b] * inv, ae[b + 1] * inv, ae[b + 2] * inv, ae[b + 3] * inv);
}

// ---------------- per-node stats of x3, x4 ----------------------------------------
__global__ void k_stats2(const float* __restrict__ x3, const float* __restrict__ x4) {
    int node = blockIdx.x * 8 + (threadIdx.x >> 5);
    if (node >= NN) return;
    int lane = threadIdx.x & 31;
    float4 a = ((const float4*)x3)[(size_t)node * 32 + lane];
    float4 b = ((const float4*)x4)[(size_t)node * 32 + lane];
    float s3  = a.x * a.x + a.y * a.y + a.z * a.z + a.w * a.w;
    float s4q = b.x * b.x + b.y * b.y + b.z * b.z + b.w * b.w;
    float s4s = b.x + b.y + b.z + b.w;
    s3 = wredsum(s3); s4q = wredsum(s4q); s4s = wredsum(s4s);
    if (lane == 0) { g_n3sq[node] = s3; g_n4sq[node] = s4q; g_s4[node] = s4s; }
}

// ---------------- fused layer-2 agg: warp per node, half-warp per edge -------------
__global__ void k_agg2(const float* __restrict__ x3, const float* __restrict__ x4) {
    int node = blockIdx.x * 8 + (threadIdx.x >> 5);
    if (node >= NN) return;
    int lane = threadIdx.x & 31;
    int half = lane >> 4, sub = lane & 15;
    const float4* x3b = (const float4*)x3;
    const float4* x4b = (const float4*)x4;
    float4 a30 = x3b[(size_t)node * 32 + sub * 2];
    float4 a31 = x3b[(size_t)node * 32 + sub * 2 + 1];
    float4 a40 = x4b[(size_t)node * 32 + sub * 2];
    float4 a41 = x4b[(size_t)node * 32 + sub * 2 + 1];
    float n3i = g_n3sq[node], n4i = g_n4sq[node], s4i = g_s4[node];
    int s = g_rowptr[node], t = g_rowptr[node + 1];
    float ac[8] = {0.f, 0.f, 0.f, 0.f, 0.f, 0.f, 0.f, 0.f};
    float ae[8] = {0.f, 0.f, 0.f, 0.f, 0.f, 0.f, 0.f, 0.f};
    for (int base = s; base < t; base += 2) {
        int j = base + half;
        bool ok = j < t;
        int c = ok ? __ldg(&g_csr[j]) : node;
        float4 v30 = x3b[(size_t)c * 32 + sub * 2];
        float4 v31 = x3b[(size_t)c * 32 + sub * 2 + 1];
        float4 v40 = x4b[(size_t)c * 32 + sub * 2];
        float4 v41 = x4b[(size_t)c * 32 + sub * 2 + 1];
        float d3 = a30.x * v30.x + a30.y * v30.y + a30.z * v30.z + a30.w * v30.w
                 + a31.x * v31.x + a31.y * v31.y + a31.z * v31.z + a31.w * v31.w;
        float d4 = a40.x * v40.x + a40.y * v40.y + a40.z * v40.z + a40.w * v40.w
                 + a41.x * v41.x + a41.y * v41.y + a41.z * v41.z + a41.w * v41.w;
#pragma unroll
        for (int o = 8; o; o >>= 1) {
            d3 += __shfl_xor_sync(0xffffffffu, d3, o);
            d4 += __shfl_xor_sync(0xffffffffu, d4, o);
        }
        float wc = d3 / fmaxf(sqrtf(n3i * g_n3sq[c]), 1e-8f);
        float q = n4i + g_n4sq[c] - 2.f * d4 + 2e-6f * (s4i - g_s4[c]) + 1.28e-10f;
        float we = sqrtf(fmaxf(q, 0.f));
        if (!ok) { wc = 0.f; we = 0.f; }
        ac[0] += wc * v30.x; ac[1] += wc * v30.y; ac[2] += wc * v30.z; ac[3] += wc * v30.w;
        ac[4] += wc * v31.x; ac[5] += wc * v31.y; ac[6] += wc * v31.z; ac[7] += wc * v31.w;
        ae[0] += we * v40.x; ae[1] += we * v40.y; ae[2] += we * v40.z; ae[3] += we * v40.w;
        ae[4] += we * v41.x; ae[5] += we * v41.y; ae[6] += we * v41.z; ae[7] += we * v41.w;
    }
#pragma unroll
    for (int i = 0; i < 8; i++) {
        ac[i] += __shfl_xor_sync(0xffffffffu, ac[i], 16);
        ae[i] += __shfl_xor_sync(0xffffffffu, ae[i], 16);
    }
    float inv = 1.f / (float)max(t - s, 1);
    int fidx = node * 32 + sub * 2 + half;
    int b = half * 4;
    ((float4*)g_aggc)[fidx] =
        make_float4(ac[b] * inv, ac[b + 1] * inv, ac[b + 2] * inv, ac[b + 3] * inv);
    ((float4*)g_agge)[fidx] =
        make_float4(ae[b] * inv, ae[b + 1] * inv, ae[b + 2] * inv, ae[b + 3] * inv);
}

// ---------------- fused weight prep: transpose + bf16 split (all 3 weight sets) ----
__global__ void k_prep_all(const float* __restrict__ Wl0, const float* __restrict__ Wr0,
                           const float* __restrict__ Wl1, const float* __restrict__ Wr1,
                           const float* __restrict__ attW1) {
    int i = blockIdx.x * blockDim.x + threadIdx.x;
    float v;
    __nv_bfloat16 *oh, *ol;
    int idx;
    if (i < 32768) {
        int n = i / 256, k = i % 256;
        v = (k < 128) ? Wl0[(size_t)k * 128 + n] : Wr0[(size_t)(k - 128) * 128 + n];
        oh = g_w0h; ol = g_w0l; idx = i;
    } else if (i < 65536) {
        int j = i - 32768;
        int n = j / 256, k = j % 256;
        v = (k < 128) ? Wl1[(size_t)k * 128 + n] : Wr1[(size_t)(k - 128) * 128 + n];
        oh = g_w1h; ol = g_w1l; idx = j;
    } else if (i < 73728) {
        int j = i - 65536;
        int n = j / 128, k = j % 128;
        v = attW1[(size_t)k * 64 + n];
        oh = g_wah; ol = g_wal; idx = j;
    } else return;
    __nv_bfloat16 h = __float2bfloat16(v);
    oh[idx] = h;
    ol[idx] = __float2bfloat16(v - __bfloat162float(h));
}

// ---------------- mma helpers ------------------------------------------------------
__device__ __forceinline__ void ldm_x4(uint32_t* r, uint32_t addr) {
    asm volatile("ldmatrix.sync.aligned.m8n8.x4.shared.b16 {%0,%1,%2,%3}, [%4];"
                 : "=r"(r[0]), "=r"(r[1]), "=r"(r[2]), "=r"(r[3]) : "r"(addr));
}
__device__ __forceinline__ void mma_bf16(float* c, const uint32_t* a, const uint32_t* b) {
    asm volatile(
        "mma.sync.aligned.m16n8k16.row.col.f32.bf16.bf16.f32 "
        "{%0,%1,%2,%3}, {%4,%5,%6,%7}, {%8,%9}, {%0,%1,%2,%3};"
        : "+f"(c[0]), "+f"(c[1]), "+f"(c[2]), "+f"(c[3])
        : "r"(a[0]), "r"(a[1]), "r"(a[2]), "r"(a[3]), "r"(b[0]), "r"(b[1]));
}
__device__ __forceinline__ uint32_t pack_bf16(float a, float b) {
    __nv_bfloat16 h0 = __float2bfloat16(a);
    __nv_bfloat16 h1 = __float2bfloat16(b);
    return (uint32_t)__bfloat16_as_ushort(h0) | ((uint32_t)__bfloat16_as_ushort(h1) << 16);
}

// ---------------- split-bf16 tensor-core GEMM (batched via blockIdx.y) -------------
// ACT: 0 none, 1 relu, 3 att (tanh + dot attW2 -> g_w[node][blockIdx.y])
template <int BN, int KT, int ACT>
__global__ __launch_bounds__(256, 2) void k_mma_gemm(
    GemmPtrs ptrs,
    const __nv_bfloat16* __restrict__ Bhg, const __nv_bfloat16* __restrict__ Blg,
    const float* __restrict__ bias, const float* __restrict__ W2,
    float* __restrict__ wout, int M) {
    constexpr int BK = 32;
    constexpr int PITCH = 40;
    constexpr int NT = BN / 16;

    __shared__ __nv_bfloat16 sAh[128 * PITCH];
    __shared__ __nv_bfloat16 sAl[128 * PITCH];
    __shared__ __nv_bfloat16 sBh[BN * PITCH];
    __shared__ __nv_bfloat16 sBl[BN * PITCH];

    const float* A1 = ptrs.A1[blockIdx.y];
    const float* A2 = ptrs.A2[blockIdx.y];
    float* Cout = ptrs.C[blockIdx.y];

    int tid = threadIdx.x, wid = tid >> 5, lane = tid & 31;
    int wm = (wid >> 1) * 32;
    int wn = (wid & 1) * (BN / 2);
    int m0 = blockIdx.x * 128;

    float acc[2][NT][4];
#pragma unroll
    for (int i = 0; i < 2; i++)
#pragma unroll
        for (int j = 0; j < NT; j++)
#pragma unroll
            for (int q = 0; q < 4; q++) acc[i][j][q] = 0.f;

    int aRow = lane & 15;
    int aColSel = (lane >> 4) * 8;
    int bRow = (lane & 7) + ((lane >> 4) << 3);
    int bColSel = ((lane >> 3) & 1) * 8;

    for (int kc = 0; kc < KT / BK; kc++) {
        int k0 = kc * BK;
        const float* As;
        int kA;
        if (KT == 256) { As = (k0 < 128) ? A1 : A2; kA = k0 & 127; }
        else           { As = A1; kA = k0; }

        {
            int r = tid >> 1, h = (tid & 1) * 16;
            int m = m0 + r;
            float4 f0, f1, f2, f3;
            if (m < M) {
                const float* s = As + (size_t)m * CD + kA + h;
                f0 = *(const float4*)(s);
                f1 = *(const float4*)(s + 4);
                f2 = *(const float4*)(s + 8);
                f3 = *(const float4*)(s + 12);
            } else {
                f0 = make_float4(0.f, 0.f, 0.f, 0.f);
                f1 = f0; f2 = f0; f3 = f0;
            }
            float fv[16] = {f0.x, f0.y, f0.z, f0.w, f1.x, f1.y, f1.z, f1.w,
                            f2.x, f2.y, f2.z, f2.w, f3.x, f3.y, f3.z, f3.w};
            uint32_t hw[8], lw[8];
#pragma unroll
            for (int j = 0; j < 8; j++) {
                float a = fv[2 * j], b = fv[2 * j + 1];
                hw[j] = pack_bf16(a, b);
                float ra = a - __bfloat162float(__ushort_as_bfloat16((uint16_t)hw[j]));
                float rb = b - __bfloat162float(__ushort_as_bfloat16((uint16_t)(hw[j] >> 16)));
                lw[j] = pack_bf16(ra, rb);
            }
            uint32_t off = (uint32_t)(r * PITCH + h);
            *(uint4*)(sAh + off)     = make_uint4(hw[0], hw[1], hw[2], hw[3]);
            *(uint4*)(sAh + off + 8) = make_uint4(hw[4], hw[5], hw[6], hw[7]);
            *(uint4*)(sAl + off)     = make_uint4(lw[0], lw[1], lw[2], lw[3]);
            *(uint4*)(sAl + off + 8) = make_uint4(lw[4], lw[5], lw[6], lw[7]);
        }
        if (tid < BN * 2) {
            int n = tid >> 1, h = (tid & 1) * 16;
            const __nv_bfloat16* gh = Bhg + (size_t)n * KT + k0 + h;
            const __nv_bfloat16* gl = Blg + (size_t)n * KT + k0 + h;
            uint4 vh0 = *(const uint4*)(gh);
            uint4 vh1 = *(const uint4*)(gh + 8);
            uint4 vl0 = *(const uint4*)(gl);
            uint4 vl1 = *(const uint4*)(gl + 8);
            uint32_t off = (uint32_t)(n * PITCH + h);
            *(uint4*)(sBh + off)     = vh0;
            *(uint4*)(sBh + off + 8) = vh1;
            *(uint4*)(sBl + off)     = vl0;
            *(uint4*)(sBl + off + 8) = vl1;
        }
        __syncthreads();

#pragma unroll
        for (int kk = 0; kk < 2; kk++) {
            int kb = kk * 16;
            uint32_t ah[2][4], al[2][4];
#pragma unroll
            for (int mt = 0; mt < 2; mt++) {
                uint32_t offA = (uint32_t)((wm + mt * 16 + aRow) * PITCH + kb + aColSel) * 2;
                ldm_x4(ah[mt], smem_u32(sAh) + offA);
                ldm_x4(al[mt], smem_u32(sAl) + offA);
            }
#pragma unroll
            for (int nt2 = 0; nt2 < NT / 2; nt2++) {
                int nb = wn + nt2 * 16;
                uint32_t offB = (uint32_t)((nb + bRow) * PITCH + kb + bColSel) * 2;
                uint32_t bh[4], bl[4];
                ldm_x4(bh, smem_u32(sBh) + offB);
                ldm_x4(bl, smem_u32(sBl) + offB);
#pragma unroll
                for (int half = 0; half < 2; half++) {
                    uint32_t bhp[2] = {bh[half * 2], bh[half * 2 + 1]};
                    uint32_t blp[2] = {bl[half * 2], bl[half * 2 + 1]};
                    int nt = nt2 * 2 + half;
#pragma unroll
                    for (int mt = 0; mt < 2; mt++) {
                        mma_bf16(acc[mt][nt], ah[mt], bhp);
                        mma_bf16(acc[mt][nt], ah[mt], blp);
                        mma_bf16(acc[mt][nt], al[mt], bhp);
                    }
                }
            }
        }
        __syncthreads();
    }

    if (ACT == 3) {
        // attention epilogue: w[m] = sum_col tanh(acc + bias[col]) * W2[col]
        __shared__ float swr[2][128];
        float wpart[2][2] = {{0.f, 0.f}, {0.f, 0.f}};
#pragma unroll
        for (int mt = 0; mt < 2; mt++) {
#pragma unroll
            for (int nt = 0; nt < NT; nt++) {
                int col = wn + nt * 8 + (lane & 3) * 2;
                float b0 = __ldg(&bias[col]), b1 = __ldg(&bias[col + 1]);
                float q0 = __ldg(&W2[col]), q1 = __ldg(&W2[col + 1]);
#pragma unroll
                for (int rh = 0; rh < 2; rh++) {
                    float v0 = acc[mt][nt][rh * 2 + 0] + b0;
                    float v1 = acc[mt][nt][rh * 2 + 1] + b1;
                    asm("tanh.approx.f32 %0, %0;" : "+f"(v0));
                    asm("tanh.approx.f32 %0, %0;" : "+f"(v1));
                    wpart[mt][rh] += v0 * q0 + v1 * q1;
                }
            }
        }
#pragma unroll
        for (int mt = 0; mt < 2; mt++)
#pragma unroll
            for (int rh = 0; rh < 2; rh++) {
                wpart[mt][rh] += __shfl_xor_sync(0xffffffffu, wpart[mt][rh], 1);
                wpart[mt][rh] += __shfl_xor_sync(0xffffffffu, wpart[mt][rh], 2);
            }
        if ((lane & 3) == 0) {
#pragma unroll
            for (int mt = 0; mt < 2; mt++)
#pragma unroll
                for (int rh = 0; rh < 2; rh++) {
                    int rloc = wm + mt * 16 + rh * 8 + (lane >> 2);
                    swr[wid & 1][rloc] = wpart[mt][rh];
                }
        }
        __syncthreads();
        if (tid < 128) {
            int m = m0 + tid;
            if (m < M) wout[(size_t)m * 4 + blockIdx.y] = swr[0][tid] + swr[1][tid];
        }
    } else {
#pragma unroll
        for (int mt = 0; mt < 2; mt++) {
#pragma unroll
            for (int nt = 0; nt < NT; nt++) {
                int col = wn + nt * 8 + (lane & 3) * 2;
                float b0 = __ldg(&bias[col]), b1 = __ldg(&bias[col + 1]);
#pragma unroll
                for (int rh = 0; rh < 2; rh++) {
                    int m = m0 + wm + mt * 16 + (lane >> 2) + rh * 8;
                    if (m < M) {
                        float v0 = acc[mt][nt][rh * 2 + 0] + b0;
                        float v1 = acc[mt][nt][rh * 2 + 1] + b1;
                        if (ACT == 1) { v0 = fmaxf(v0, 0.f); v1 = fmaxf(v1, 0.f); }
                        *(float2*)(Cout + (size_t)m * BN + col) = make_float2(v0, v1);
                    }
                }
            }
        }
    }
}

// ---------------- attention pooling (warp per node) -------------------------------
__global__ void k_pool(const float* __restrict__ x3, const float* __restrict__ x4,
                       float* __restrict__ emb) {
    int node = blockIdx.x * 8 + (threadIdx.x >> 5);
    if (node >= NN) return;
    int lane = threadIdx.x & 31;
    float4 wv = ((const float4*)g_w)[node];
    float m = fmaxf(fmaxf(wv.x, wv.y), fmaxf(wv.z, wv.w));
    float e0 = __expf(wv.x - m), e1 = __expf(wv.y - m);
    float e2 = __expf(wv.z - m), e3 = __expf(wv.w - m);
    float inv = 1.f / (e0 + e1 + e2 + e3);
    float b0 = e0 * inv, b1 = e1 * inv, b2 = e2 * inv, b3 = e3 * inv;
    float4 v1 = ((const float4*)g_x1)[(size_t)node * 32 + lane];
    float4 v2 = ((const float4*)g_x2)[(size_t)node * 32 + lane];
    float4 v3 = ((const float4*)x3)[(size_t)node * 32 + lane];
    float4 v4 = ((const float4*)x4)[(size_t)node * 32 + lane];
    float4 r;
    r.x = b0 * v1.x + b1 * v2.x + b2 * v3.x + b3 * v4.x;
    r.y = b0 * v1.y + b1 * v2.y + b2 * v3.y + b3 * v4.y;
    r.z = b0 * v1.z + b1 * v2.z + b2 * v3.z + b3 * v4.z;
    r.w = b0 * v1.w + b1 * v2.w + b2 * v3.w + b3 * v4.w;
    ((float4*)emb)[(size_t)node * 32 + lane] = r;
}

// ---------------- host ------------------------------------------------------------
extern "C" void kernel_launch(void* const* d_in, const int* in_sizes, int n_in,
                              void* d_out, int out_size) {
    const float* x     = (const float*)d_in[0];
    const int*   row   = (const int*)d_in[1];
    const int*   col   = (const int*)d_in[2];
    const float* Wl0   = (const float*)d_in[3];
    const float* bl0   = (const float*)d_in[4];
    const float* Wr0   = (const float*)d_in[5];
    const float* Wl1   = (const float*)d_in[6];
    const float* bl1   = (const float*)d_in[7];
    const float* Wr1   = (const float*)d_in[8];
    const float* attW1 = (const float*)d_in[9];
    const float* attb1 = (const float*)d_in[10];
    const float* attW2 = (const float*)d_in[11];

    float* out = (float*)d_out;
    float* emb = out;
    float* x3  = out + (size_t)NN * CD;
    float* x4  = out + (size_t)2 * NN * CD;

    void* pdegcur;
    float *aggc, *agge, *x1b, *x2b, *wbuf;
    __nv_bfloat16 *w0h, *w0l, *w1h, *w1l, *wah, *wal;
    cudaGetSymbolAddress(&pdegcur, g_degcur);
    cudaGetSymbolAddress((void**)&aggc, g_aggc);
    cudaGetSymbolAddress((void**)&agge, g_agge);
    cudaGetSymbolAddress((void**)&x1b, g_x1);
    cudaGetSymbolAddress((void**)&x2b, g_x2);
    cudaGetSymbolAddress((void**)&wbuf, g_w);
    cudaGetSymbolAddress((void**)&w0h, g_w0h);
    cudaGetSymbolAddress((void**)&w0l, g_w0l);
    cudaGetSymbolAddress((void**)&w1h, g_w1h);
    cudaGetSymbolAddress((void**)&w1l, g_w1l);
    cudaGetSymbolAddress((void**)&wah, g_wah);
    cudaGetSymbolAddress((void**)&wal, g_wal);

    const int nodeBlocks = (NN + 7) / 8;
    const int edgeBlocks = (NE + 255) / 256;
    const int TG = (NN + 127) / 128;

    // launch order chosen so k_agg1 is launch #5 (ncu -s 5 -c 1 profiles it)
    cudaMemsetAsync(pdegcur, 0, 2 * NN * sizeof(int));        // 0
    k_stats1<<<nodeBlocks, 256>>>(x);                         // 1
    k_deg<<<edgeBlocks, 256>>>(row);                          // 2
    k_scan<<<1, 1024>>>();                                    // 3
    k_scatter<<<edgeBlocks, 256>>>(row, col);                 // 4
    k_agg1<<<nodeBlocks, 256>>>(x);                           // 5  <- profiled

    k_prep_all<<<288, 256>>>(Wl0, Wr0, Wl1, Wr1, attW1);      // 6

    // layer 1 (batched): x3 = relu([aggc|x]@W0+bl0), x4 = relu([agge|x]@W0+bl0)
    {
        GemmPtrs p = {};
        p.A1[0] = aggc; p.A2[0] = x; p.C[0] = x3;
        p.A1[1] = agge; p.A2[1] = x; p.C[1] = x4;
        k_mma_gemm<128, 256, 1><<<dim3(TG, 2), 256>>>(p, w0h, w0l, bl0, nullptr, nullptr, NN);
    }

    k_stats2<<<nodeBlocks, 256>>>(x3, x4);
    k_agg2<<<nodeBlocks, 256>>>(x3, x4);

    // layer 2 (batched)
    {
        GemmPtrs p = {};
        p.A1[0] = aggc; p.A2[0] = x3; p.C[0] = x1b;
        p.A1[1] = agge; p.A2[1] = x4; p.C[1] = x2b;
        k_mma_gemm<128, 256, 0><<<dim3(TG, 2), 256>>>(p, w1h, w1l, bl1, nullptr, nullptr, NN);
    }

    // attention logits (batched, 4 branches): w[n][k] = tanh(Xk@attW1+attb1)@attW2
    {
        GemmPtrs p = {};
        p.A1[0] = x1b; p.A1[1] = x2b; p.A1[2] = x3; p.A1[3] = x4;
        k_mma_gemm<64, 128, 3><<<dim3(TG, 4), 256>>>(p, wah, wal, attb1, attW2, wbuf, NN);
    }

    k_pool<<<nodeBlocks, 256>>>(x3, x4, emb);
}